// round 3
// baseline (speedup 1.0000x reference)
#include <cuda_runtime.h>
#include <math.h>

#define B 32
#define TIN 512
#define TOUT 800
#define NMEL 80
#define ENC 512
#define ARNN 1024
#define DRNN 1024
#define PRE 256
#define ATT 128
#define LOCF 32
#define LOCK 31
#define NB 128

// ---------------- device state (batch-minor [k][b] for recurrent vectors) ----------------
static __device__ float g_pren[(size_t)TOUT * PRE * B];   // [t][j][b]
static __device__ float g_pmemT[(size_t)B * ATT * TIN];   // [b][a][t]
static __device__ float g_ah[2][ARNN * B];                // [h][b]
static __device__ float g_ahbm[2][B * ARNN];              // [b][h]
static __device__ float g_ac[ARNN * B];
static __device__ float g_dh[2][DRNN * B];
static __device__ float g_dhbm[2][B * DRNN];
static __device__ float g_dc[DRNN * B];
static __device__ float g_aw[B * TIN];
static __device__ float g_awc[B * TIN];
static __device__ float g_actx[ENC * B];                  // [d][b]
static __device__ float g_actxbm[B * ENC];                // [b][d]
static __device__ float g_energy[B * TIN];
static __device__ unsigned g_count = 0;
static __device__ volatile unsigned g_epoch = 0;

__device__ __forceinline__ float sigf(float x) { return __fdividef(1.f, 1.f + __expf(-x)); }
__device__ __forceinline__ float tanha(float x) {
    float y; asm("tanh.approx.f32 %0, %1;" : "=f"(y) : "f"(x)); return y;
}
__device__ __forceinline__ float wsum(float v) {
#pragma unroll
    for (int o = 16; o > 0; o >>= 1) v += __shfl_xor_sync(0xffffffffu, v, o);
    return v;
}

// ---------------- grid barrier (all NB blocks co-resident) ----------------
__device__ __forceinline__ void gbar() {
    __syncthreads();
    if (threadIdx.x == 0) {
        unsigned e = g_epoch;
        __threadfence();
        if (atomicAdd(&g_count, 1) == NB - 1) {
            atomicExch(&g_count, 0);
            __threadfence();
            g_epoch = e + 1;
        } else {
            while (g_epoch == e) { }
        }
        __threadfence();
    }
    __syncthreads();
}

// ---------------- shared memory union ----------------
struct SLstm { float xs[64][B]; float zs[4][8][B]; };
struct SAtt {
    float pqs[ATT]; float vs[ATT];
    float cat0[158]; float cat1[158];
    float cwsT[62][32];        // transposed conv weights [kc][f]
    float lls[ATT * LOCF];     // [a][f]
    float ep[256];
    union { float ahs[ARNN]; float lfs[128][LOCF + 1]; } u;
};
struct SSoft { float sw[TIN]; float red[8]; };
struct SProj { float sd[DRNN + ENC]; };
union Smem { SLstm l; SAtt a; SSoft s; SProj p; };

// ---------------- init ----------------
__global__ void zero_kernel() {
    int i = blockIdx.x * blockDim.x + threadIdx.x;
    if (i < ARNN * B) {
        g_ah[0][i] = 0.f; g_ah[1][i] = 0.f; g_ahbm[0][i] = 0.f; g_ahbm[1][i] = 0.f; g_ac[i] = 0.f;
        g_dh[0][i] = 0.f; g_dh[1][i] = 0.f; g_dhbm[0][i] = 0.f; g_dhbm[1][i] = 0.f; g_dc[i] = 0.f;
    }
    if (i < B * TIN) { g_aw[i] = 0.f; g_awc[i] = 0.f; }
    if (i < ENC * B) { g_actx[i] = 0.f; }
}

// ---------------- prenet precompute -> g_pren[t][j][b] ----------------
__global__ __launch_bounds__(256)
void prenet_kernel(const float* __restrict__ dec, const float* __restrict__ w1,
                   const float* __restrict__ w2) {
    int t = blockIdx.x >> 5;
    int b = blockIdx.x & 31;
    int tid = threadIdx.x;
    __shared__ float xm[NMEL];
    __shared__ float x1[PRE];
    if (tid < NMEL)
        xm[tid] = (t == 0) ? 0.f : dec[(size_t)b * NMEL * TOUT + (size_t)tid * TOUT + (t - 1)];
    __syncthreads();
    {
        const float* w = w1 + tid * NMEL;
        float s = 0.f;
#pragma unroll
        for (int m = 0; m < NMEL; ++m) s += xm[m] * w[m];
        x1[tid] = fmaxf(s, 0.f);
    }
    __syncthreads();
    {
        const float* w = w2 + tid * PRE;
        float s = 0.f;
#pragma unroll 8
        for (int k = 0; k < PRE; ++k) s += x1[k] * w[k];
        g_pren[((size_t)t * PRE + tid) * B + b] = fmaxf(s, 0.f);
    }
}

// ---------------- pmemT precompute -> [b][a][t] ----------------
__global__ __launch_bounds__(128)
void pmem_kernel(const float* __restrict__ memory, const float* __restrict__ memw) {
    int b = blockIdx.x;
    int tb = blockIdx.y * 16;
    int a = threadIdx.x;
    __shared__ __align__(16) float xs[64][16];
    __shared__ float ws[128 * 65];
    float acc[16];
#pragma unroll
    for (int i = 0; i < 16; ++i) acc[i] = 0.f;
    for (int e0 = 0; e0 < ENC; e0 += 64) {
        __syncthreads();
#pragma unroll
        for (int i2 = 0; i2 < 8; ++i2) {
            int idx = a + i2 * 128;
            int ee = idx & 63, tt = idx >> 6;
            xs[ee][tt] = memory[(size_t)b * TIN * ENC + (size_t)(tb + tt) * ENC + e0 + ee];
        }
#pragma unroll
        for (int i2 = 0; i2 < 64; ++i2) {
            int idx = a + i2 * 128;
            int ee = idx & 63, aa = idx >> 6;
            ws[aa * 65 + ee] = memw[aa * ENC + e0 + ee];
        }
        __syncthreads();
#pragma unroll 4
        for (int ee = 0; ee < 64; ++ee) {
            float w = ws[a * 65 + ee];
            const float4* xr = (const float4*)&xs[ee][0];
            float4 v0 = xr[0], v1 = xr[1], v2 = xr[2], v3 = xr[3];
            acc[0] += w * v0.x; acc[1] += w * v0.y; acc[2] += w * v0.z; acc[3] += w * v0.w;
            acc[4] += w * v1.x; acc[5] += w * v1.y; acc[6] += w * v1.z; acc[7] += w * v1.w;
            acc[8] += w * v2.x; acc[9] += w * v2.y; acc[10] += w * v2.z; acc[11] += w * v2.w;
            acc[12] += w * v3.x; acc[13] += w * v3.y; acc[14] += w * v3.z; acc[15] += w * v3.w;
        }
    }
    float* o = g_pmemT + (size_t)b * ATT * TIN + (size_t)a * TIN + tb;
#pragma unroll
    for (int i = 0; i < 16; ++i) o[i] = acc[i];
}

// ---------------- LSTM phase: x=[srcA(WA);srcB(WB)], recurrent over hprev (1024) ------
template <int WA, int WB>
__device__ void lstm_phase(const float* __restrict__ srcA, const float* __restrict__ srcB,
                           const float* __restrict__ hprev,
                           const float* __restrict__ wih, const float* __restrict__ whh,
                           const float* __restrict__ bih, const float* __restrict__ bhh,
                           float* __restrict__ cst, float* __restrict__ hout,
                           float* __restrict__ houtbm, SLstm& s) {
    constexpr int KX = WA + WB;
    constexpr int KTOT = KX + 1024;
    const int tid = threadIdx.x;
    const int row = tid >> 3, bg = tid & 7;
    const int gg = row >> 3, hh = row & 7;
    const int h0 = blockIdx.x * 8;
    const int j = gg * 1024 + h0 + hh;
    const float* wih_row = wih + (size_t)j * KX;
    const float* whh_row = whh + (size_t)j * 1024;
    float a0 = 0.f, a1 = 0.f, a2 = 0.f, a3 = 0.f;
    for (int k0 = 0; k0 < KTOT; k0 += 64) {
        __syncthreads();
#pragma unroll
        for (int i2 = 0; i2 < 8; ++i2) {
            int idx = tid + i2 * 256;
            int kk = idx >> 5, bb = idx & 31;
            int k = k0 + kk;
            float v;
            if (k < WA) v = srcA[k * B + bb];
            else if (k < KX) v = srcB[(k - WA) * B + bb];
            else v = hprev[(k - KX) * B + bb];
            s.xs[kk][bb] = v;
        }
        __syncthreads();
        const float* wr = (k0 < KX) ? (wih_row + k0) : (whh_row + (k0 - KX));
#pragma unroll 4
        for (int kk = 0; kk < 64; kk += 4) {
            float4 wv = __ldg((const float4*)(wr + kk));
            float4 x;
            x = *(const float4*)&s.xs[kk + 0][bg * 4];
            a0 += wv.x * x.x; a1 += wv.x * x.y; a2 += wv.x * x.z; a3 += wv.x * x.w;
            x = *(const float4*)&s.xs[kk + 1][bg * 4];
            a0 += wv.y * x.x; a1 += wv.y * x.y; a2 += wv.y * x.z; a3 += wv.y * x.w;
            x = *(const float4*)&s.xs[kk + 2][bg * 4];
            a0 += wv.z * x.x; a1 += wv.z * x.y; a2 += wv.z * x.z; a3 += wv.z * x.w;
            x = *(const float4*)&s.xs[kk + 3][bg * 4];
            a0 += wv.w * x.x; a1 += wv.w * x.y; a2 += wv.w * x.z; a3 += wv.w * x.w;
        }
    }
    float bias = bih[j] + bhh[j];
    s.zs[gg][hh][bg * 4 + 0] = a0 + bias;
    s.zs[gg][hh][bg * 4 + 1] = a1 + bias;
    s.zs[gg][hh][bg * 4 + 2] = a2 + bias;
    s.zs[gg][hh][bg * 4 + 3] = a3 + bias;
    __syncthreads();
    const int b2 = tid & 31, hh2 = tid >> 5;
    const int h = h0 + hh2;
    float zi = s.zs[0][hh2][b2], zf = s.zs[1][hh2][b2];
    float zg = s.zs[2][hh2][b2], zo = s.zs[3][hh2][b2];
    float c = cst[h * B + b2];
    float cn = sigf(zf) * c + sigf(zi) * tanhf(zg);
    cst[h * B + b2] = cn;
    float hv = sigf(zo) * tanhf(cn);
    hout[h * B + b2] = hv;
    houtbm[b2 * 1024 + h] = hv;
}

// ---------------- attention phase: pq + location conv + energies ----------------
__device__ void att_phase(const float* __restrict__ qw, const float* __restrict__ convw,
                          const float* __restrict__ loclin, const float* __restrict__ vw,
                          const int* __restrict__ lens, int cur, SAtt& s) {
    const int tid = threadIdx.x;
    const int b = blockIdx.x >> 2;
    const int tbase = (blockIdx.x & 3) * 128;
    const int warp = tid >> 5, lane = tid & 31;
    // loads
    const float4* ahsrc = (const float4*)&g_ahbm[cur][b * ARNN];
#pragma unroll
    for (int i = 0; i < 1; ++i) ((float4*)s.u.ahs)[tid] = ahsrc[tid];
    for (int i = tid; i < 62 * 32; i += 256) s.cwsT[i >> 5][i & 31] = convw[(i & 31) * 62 + (i >> 5)];
    for (int i = tid; i < ATT * LOCF; i += 256) s.lls[i] = loclin[i];
    if (tid < ATT) { s.vs[tid] = vw[tid]; }
    for (int i = tid; i < 158; i += 256) {
        int tp = tbase - 15 + i;
        bool ok = (tp >= 0 && tp < TIN);
        s.cat0[i] = ok ? g_aw[b * TIN + tp] : 0.f;
        s.cat1[i] = ok ? g_awc[b * TIN + tp] : 0.f;
    }
    __syncthreads();
    // pq: 8 warps x 16 rows of q_w (dot 1024)
    for (int r = 0; r < 16; ++r) {
        int a = warp * 16 + r;
        const float4* w = (const float4*)(qw + (size_t)a * ARNN);
        const float4* hv = (const float4*)s.u.ahs;
        float acc = 0.f;
#pragma unroll
        for (int i = 0; i < 8; ++i) {
            float4 wv = __ldg(&w[lane + i * 32]);
            float4 xv = hv[lane + i * 32];
            acc += wv.x * xv.x + wv.y * xv.y + wv.z * xv.z + wv.w * xv.w;
        }
        acc = wsum(acc);
        if (lane == 0) s.pqs[a] = acc;
    }
    __syncthreads();   // ahs dead; lfs may now overwrite
    // conv: thread (t, half) computes 16 filters
    {
        const int t = tid & 127, half = tid >> 7;
        float lf[16];
#pragma unroll
        for (int i = 0; i < 16; ++i) lf[i] = 0.f;
#pragma unroll 2
        for (int kc = 0; kc < 62; ++kc) {
            float c = (kc < 31) ? s.cat0[t + kc] : s.cat1[t + kc - 31];
            const float4* w = (const float4*)&s.cwsT[kc][half * 16];
            float4 w0 = w[0], w1 = w[1], w2 = w[2], w3 = w[3];
            lf[0] += c * w0.x; lf[1] += c * w0.y; lf[2] += c * w0.z; lf[3] += c * w0.w;
            lf[4] += c * w1.x; lf[5] += c * w1.y; lf[6] += c * w1.z; lf[7] += c * w1.w;
            lf[8] += c * w2.x; lf[9] += c * w2.y; lf[10] += c * w2.z; lf[11] += c * w2.w;
            lf[12] += c * w3.x; lf[13] += c * w3.y; lf[14] += c * w3.z; lf[15] += c * w3.w;
        }
#pragma unroll
        for (int i = 0; i < 16; ++i) s.u.lfs[t][half * 16 + i] = lf[i];
    }
    __syncthreads();
    // energies: thread (t, half) handles 64 attention dims
    {
        const int t = tid & 127, half = tid >> 7;
        float lfr[32];
#pragma unroll
        for (int i = 0; i < 32; ++i) lfr[i] = s.u.lfs[t][i];
        const float* pm = g_pmemT + (size_t)b * ATT * TIN + tbase + t;
        float e = 0.f;
#pragma unroll 2
        for (int a = half * 64; a < half * 64 + 64; ++a) {
            float s0 = s.pqs[a] + __ldg(&pm[(size_t)a * TIN]);
            const float4* ll = (const float4*)&s.lls[a * LOCF];
#pragma unroll
            for (int i = 0; i < 8; ++i) {
                float4 lv = ll[i];
                s0 += lv.x * lfr[i * 4] + lv.y * lfr[i * 4 + 1] + lv.z * lfr[i * 4 + 2] + lv.w * lfr[i * 4 + 3];
            }
            e += s.vs[a] * tanha(s0);
        }
        s.ep[tid] = e;
    }
    __syncthreads();
    if (tid < 128) {
        int tp = tbase + tid;
        float e = s.ep[tid] + s.ep[tid + 128];
        if (tp >= lens[b]) e = -1e9f;
        g_energy[b * TIN + tp] = e;
    }
}

// ---------------- softmax + context (blocks < 32) ----------------
__device__ void softctx_phase(const float* __restrict__ memory, int t,
                              float* __restrict__ out_align, SSoft& s) {
    const int b = blockIdx.x, tid = threadIdx.x;
    const int warp = tid >> 5, lane = tid & 31;
    float2 e2 = *(const float2*)&g_energy[b * TIN + tid * 2];
    float m = fmaxf(e2.x, e2.y);
#pragma unroll
    for (int o = 16; o > 0; o >>= 1) m = fmaxf(m, __shfl_xor_sync(0xffffffffu, m, o));
    if (lane == 0) s.red[warp] = m;
    __syncthreads();
    float mm = s.red[lane & 7];
#pragma unroll
    for (int o = 4; o > 0; o >>= 1) mm = fmaxf(mm, __shfl_xor_sync(0xffffffffu, mm, o));
    m = mm;
    float p0 = __expf(e2.x - m), p1 = __expf(e2.y - m);
    float ps = p0 + p1;
#pragma unroll
    for (int o = 16; o > 0; o >>= 1) ps += __shfl_xor_sync(0xffffffffu, ps, o);
    __syncthreads();
    if (lane == 0) s.red[warp] = ps;
    __syncthreads();
    float ss = s.red[lane & 7];
#pragma unroll
    for (int o = 4; o > 0; o >>= 1) ss += __shfl_xor_sync(0xffffffffu, ss, o);
    float inv = __fdividef(1.f, ss);
    float a0 = p0 * inv, a1 = p1 * inv;
    s.sw[tid * 2] = a0; s.sw[tid * 2 + 1] = a1;
    g_aw[b * TIN + tid * 2] = a0; g_aw[b * TIN + tid * 2 + 1] = a1;
    g_awc[b * TIN + tid * 2] += a0; g_awc[b * TIN + tid * 2 + 1] += a1;
    float* oa = out_align + ((size_t)b * TOUT + t) * TIN + tid * 2;
    oa[0] = a0; oa[1] = a1;
    __syncthreads();
    const float* mb = memory + (size_t)b * TIN * ENC + tid;
    float acc0 = 0.f, acc1 = 0.f;
#pragma unroll 4
    for (int tt = 0; tt < TIN; ++tt) {
        float w = s.sw[tt];
        acc0 += w * __ldg(&mb[(size_t)tt * ENC]);
        acc1 += w * __ldg(&mb[(size_t)tt * ENC + 256]);
    }
    g_actx[tid * B + b] = acc0;
    g_actx[(tid + 256) * B + b] = acc1;
    g_actxbm[b * ENC + tid] = acc0;
    g_actxbm[b * ENC + tid + 256] = acc1;
}

// ---------------- projection + gate (blocks < 32) ----------------
__device__ void proj_phase(const float* __restrict__ pw, const float* __restrict__ pb,
                           const float* __restrict__ gw, const float* __restrict__ gb,
                           int t, int cur, float* __restrict__ out_mel,
                           float* __restrict__ out_gate, SProj& s) {
    const int b = blockIdx.x, tid = threadIdx.x;
    const int warp = tid >> 5, lane = tid & 31;
    for (int i = tid; i < DRNN; i += 256) s.sd[i] = g_dhbm[cur][b * DRNN + i];
    for (int i = tid; i < ENC; i += 256) s.sd[DRNN + i] = g_actxbm[b * ENC + i];
    __syncthreads();
    for (int r = warp; r < NMEL + 1; r += 8) {
        const float4* w = (const float4*)((r < NMEL) ? (pw + (size_t)r * (DRNN + ENC)) : gw);
        const float4* x = (const float4*)s.sd;
        float acc = 0.f;
#pragma unroll
        for (int i = 0; i < 12; ++i) {
            float4 wv = __ldg(&w[lane + i * 32]);
            float4 xv = x[lane + i * 32];
            acc += wv.x * xv.x + wv.y * xv.y + wv.z * xv.z + wv.w * xv.w;
        }
        acc = wsum(acc);
        if (lane == 0) {
            if (r < NMEL) out_mel[(size_t)b * NMEL * TOUT + (size_t)r * TOUT + t] = acc + pb[r];
            else out_gate[(size_t)b * TOUT + t] = acc + gb[0];
        }
    }
}

// ---------------- persistent decoder ----------------
__global__ __launch_bounds__(256)
void persist_kernel(const float* __restrict__ memory,
                    const float* __restrict__ awih, const float* __restrict__ awhh,
                    const float* __restrict__ abih, const float* __restrict__ abhh,
                    const float* __restrict__ qw, const float* __restrict__ vw,
                    const float* __restrict__ convw, const float* __restrict__ loclin,
                    const float* __restrict__ dwih, const float* __restrict__ dwhh,
                    const float* __restrict__ dbih, const float* __restrict__ dbhh,
                    const float* __restrict__ pw, const float* __restrict__ pb,
                    const float* __restrict__ gw, const float* __restrict__ gb,
                    const int* __restrict__ lens,
                    float* __restrict__ out_mel, float* __restrict__ out_gate,
                    float* __restrict__ out_align) {
    __shared__ Smem sm;
    for (int t = 0; t < TOUT; ++t) {
        const int cur = t & 1, prev = cur ^ 1;
        lstm_phase<PRE, ENC>(g_pren + (size_t)t * PRE * B, g_actx, &g_ah[prev][0],
                             awih, awhh, abih, abhh, g_ac, &g_ah[cur][0], &g_ahbm[cur][0], sm.l);
        gbar();
        att_phase(qw, convw, loclin, vw, lens, cur, sm.a);
        gbar();
        if (blockIdx.x < 32) softctx_phase(memory, t, out_align, sm.s);
        gbar();
        lstm_phase<ARNN, ENC>(&g_ah[cur][0], g_actx, &g_dh[prev][0],
                              dwih, dwhh, dbih, dbhh, g_dc, &g_dh[cur][0], &g_dhbm[cur][0], sm.l);
        gbar();
        if (blockIdx.x < 32) proj_phase(pw, pb, gw, gb, t, cur, out_mel, out_gate, sm.p);
    }
}

// ---------------- launch ----------------
extern "C" void kernel_launch(void* const* d_in, const int* in_sizes, int n_in,
                              void* d_out, int out_size) {
    const float* memory = (const float*)d_in[0];
    const float* dec    = (const float*)d_in[1];
    const float* w1     = (const float*)d_in[2];
    const float* w2     = (const float*)d_in[3];
    const float* awih   = (const float*)d_in[4];
    const float* awhh   = (const float*)d_in[5];
    const float* abih   = (const float*)d_in[6];
    const float* abhh   = (const float*)d_in[7];
    const float* qw     = (const float*)d_in[8];
    const float* memw   = (const float*)d_in[9];
    const float* vw     = (const float*)d_in[10];
    const float* convw  = (const float*)d_in[11];
    const float* loclin = (const float*)d_in[12];
    const float* dwih   = (const float*)d_in[13];
    const float* dwhh   = (const float*)d_in[14];
    const float* dbih   = (const float*)d_in[15];
    const float* dbhh   = (const float*)d_in[16];
    const float* pw     = (const float*)d_in[17];
    const float* pb     = (const float*)d_in[18];
    const float* gw     = (const float*)d_in[19];
    const float* gb     = (const float*)d_in[20];
    const int*   lens   = (const int*)d_in[21];

    float* out_mel = (float*)d_out;
    float* out_gate = out_mel + (size_t)B * NMEL * TOUT;
    float* out_align = out_gate + (size_t)B * TOUT;

    zero_kernel<<<(ARNN * B + 255) / 256, 256>>>();
    prenet_kernel<<<TOUT * B, 256>>>(dec, w1, w2);
    pmem_kernel<<<dim3(B, TIN / 16), 128>>>(memory, memw);
    persist_kernel<<<NB, 256>>>(memory, awih, awhh, abih, abhh, qw, vw, convw, loclin,
                                dwih, dwhh, dbih, dbhh, pw, pb, gw, gb, lens,
                                out_mel, out_gate, out_align);
}

// round 4
// speedup vs baseline: 1.4918x; 1.4918x over previous
#include <cuda_runtime.h>
#include <math.h>

#define B 32
#define TIN 512
#define TOUT 800
#define NMEL 80
#define ENC 512
#define ARNN 1024
#define DRNN 1024
#define PRE 256
#define ATT 128
#define LOCF 32
#define LOCK 31
#define NB 128

// ---------------- device state ----------------
static __device__ float g_pren[(size_t)TOUT * PRE * B];   // [t][j][b]
static __device__ float g_pmemT[(size_t)B * ATT * TIN];   // [b][a][t]
static __device__ float g_ah[2][ARNN * B];                // [h][b]
static __device__ float g_ahbm[2][B * ARNN];              // [b][h]
static __device__ float g_ac[ARNN * B];
static __device__ float g_dh[2][DRNN * B];
static __device__ float g_dhbm[2][B * DRNN];
static __device__ float g_dc[DRNN * B];
static __device__ float g_aw[B * TIN];
static __device__ float g_awc[B * TIN];
static __device__ float g_actx[ENC * B];                  // [d][b]
static __device__ float g_actxbm[B * ENC];                // [b][d]
static __device__ __align__(128) unsigned g_count;
static __device__ __align__(128) volatile unsigned g_epoch;

__device__ __forceinline__ float sigf(float x) { return __fdividef(1.f, 1.f + __expf(-x)); }
__device__ __forceinline__ float tanha(float x) {
    float y; asm("tanh.approx.f32 %0, %1;" : "=f"(y) : "f"(x)); return y;
}
__device__ __forceinline__ float wsum(float v) {
#pragma unroll
    for (int o = 16; o > 0; o >>= 1) v += __shfl_xor_sync(0xffffffffu, v, o);
    return v;
}
__device__ __forceinline__ float wmax(float v) {
#pragma unroll
    for (int o = 16; o > 0; o >>= 1) v = fmaxf(v, __shfl_xor_sync(0xffffffffu, v, o));
    return v;
}

// ---------------- grid barrier ----------------
__device__ __forceinline__ void gbar() {
    __syncthreads();
    if (threadIdx.x == 0) {
        unsigned e = g_epoch;
        __threadfence();
        if (atomicAdd(&g_count, 1) == NB - 1) {
            g_count = 0;
            __threadfence();
            g_epoch = e + 1;
        } else {
            while (g_epoch == e) __nanosleep(64);
        }
        __threadfence();
    }
    __syncthreads();
}

// ---------------- shared memory ----------------
struct SLstm { float xs[2][64][B]; float zs[4][8][B]; };
struct SAtt {
    float ahs[ARNN];
    float pqs[ATT]; float vs[ATT];
    float cat0[TIN + 30]; float cat1[TIN + 30];
    float cwsT[62][LOCF];
    float lls[ATT * LOCF];
    float sw[TIN];
    float red[8];
};
struct SProj { float sd[DRNN + ENC]; };
union Smem { SLstm l; SAtt a; SProj p; };

// ---------------- init ----------------
__global__ void zero_kernel() {
    int i = blockIdx.x * blockDim.x + threadIdx.x;
    if (i < ARNN * B) {
        g_ah[0][i] = 0.f; g_ah[1][i] = 0.f; g_ahbm[0][i] = 0.f; g_ahbm[1][i] = 0.f; g_ac[i] = 0.f;
        g_dh[0][i] = 0.f; g_dh[1][i] = 0.f; g_dhbm[0][i] = 0.f; g_dhbm[1][i] = 0.f; g_dc[i] = 0.f;
    }
    if (i < B * TIN) { g_aw[i] = 0.f; g_awc[i] = 0.f; }
    if (i < ENC * B) { g_actx[i] = 0.f; }
    if (i == 0) { g_count = 0; g_epoch = 0; }
}

// ---------------- prenet precompute -> g_pren[t][j][b] ----------------
__global__ __launch_bounds__(256)
void prenet_kernel(const float* __restrict__ dec, const float* __restrict__ w1,
                   const float* __restrict__ w2) {
    int t = blockIdx.x >> 5;
    int b = blockIdx.x & 31;
    int tid = threadIdx.x;
    __shared__ float xm[NMEL];
    __shared__ float x1[PRE];
    if (tid < NMEL)
        xm[tid] = (t == 0) ? 0.f : dec[(size_t)b * NMEL * TOUT + (size_t)tid * TOUT + (t - 1)];
    __syncthreads();
    {
        const float* w = w1 + tid * NMEL;
        float s = 0.f;
#pragma unroll
        for (int m = 0; m < NMEL; ++m) s += xm[m] * w[m];
        x1[tid] = fmaxf(s, 0.f);
    }
    __syncthreads();
    {
        const float* w = w2 + tid * PRE;
        float s = 0.f;
#pragma unroll 8
        for (int k = 0; k < PRE; ++k) s += x1[k] * w[k];
        g_pren[((size_t)t * PRE + tid) * B + b] = fmaxf(s, 0.f);
    }
}

// ---------------- pmemT precompute -> [b][a][t] ----------------
__global__ __launch_bounds__(128)
void pmem_kernel(const float* __restrict__ memory, const float* __restrict__ memw) {
    int b = blockIdx.x;
    int tb = blockIdx.y * 16;
    int a = threadIdx.x;
    __shared__ __align__(16) float xs[64][16];
    __shared__ float ws[128 * 65];
    float acc[16];
#pragma unroll
    for (int i = 0; i < 16; ++i) acc[i] = 0.f;
    for (int e0 = 0; e0 < ENC; e0 += 64) {
        __syncthreads();
#pragma unroll
        for (int i2 = 0; i2 < 8; ++i2) {
            int idx = a + i2 * 128;
            int ee = idx & 63, tt = idx >> 6;
            xs[ee][tt] = memory[(size_t)b * TIN * ENC + (size_t)(tb + tt) * ENC + e0 + ee];
        }
#pragma unroll
        for (int i2 = 0; i2 < 64; ++i2) {
            int idx = a + i2 * 128;
            int ee = idx & 63, aa = idx >> 6;
            ws[aa * 65 + ee] = memw[aa * ENC + e0 + ee];
        }
        __syncthreads();
#pragma unroll 4
        for (int ee = 0; ee < 64; ++ee) {
            float w = ws[a * 65 + ee];
            const float4* xr = (const float4*)&xs[ee][0];
            float4 v0 = xr[0], v1 = xr[1], v2 = xr[2], v3 = xr[3];
            acc[0] += w * v0.x; acc[1] += w * v0.y; acc[2] += w * v0.z; acc[3] += w * v0.w;
            acc[4] += w * v1.x; acc[5] += w * v1.y; acc[6] += w * v1.z; acc[7] += w * v1.w;
            acc[8] += w * v2.x; acc[9] += w * v2.y; acc[10] += w * v2.z; acc[11] += w * v2.w;
            acc[12] += w * v3.x; acc[13] += w * v3.y; acc[14] += w * v3.z; acc[15] += w * v3.w;
        }
    }
    float* o = g_pmemT + (size_t)b * ATT * TIN + (size_t)a * TIN + tb;
#pragma unroll
    for (int i = 0; i < 16; ++i) o[i] = acc[i];
}

// ---------------- LSTM phase: MLP-16 weight prefetch + double-buffered x staging ----
template <int WA, int WB>
__device__ void lstm_phase(const float* __restrict__ srcA, const float* __restrict__ srcB,
                           const float* __restrict__ hprev,
                           const float* __restrict__ wih, const float* __restrict__ whh,
                           const float* __restrict__ bih, const float* __restrict__ bhh,
                           float* __restrict__ cst, float* __restrict__ hout,
                           float* __restrict__ houtbm, SLstm& s) {
    constexpr int KX = WA + WB;
    constexpr int KTOT = KX + 1024;
    constexpr int NC = KTOT / 64;
    const int tid = threadIdx.x;
    const int row = tid >> 3, bg = tid & 7;
    const int gg = row >> 3, hh = row & 7;
    const int h0 = blockIdx.x * 8;
    const int j = gg * 1024 + h0 + hh;
    const float* wihr = wih + (size_t)j * KX;
    const float* whhr = whh + (size_t)j * 1024;
    float a0 = 0.f, a1 = 0.f, a2 = 0.f, a3 = 0.f;
    // prologue: stage chunk 0
#pragma unroll
    for (int i = 0; i < 8; ++i) {
        int idx = tid + i * 256;
        int kk = idx >> 5, bb = idx & 31;
        float v;
        if (kk < WA) v = srcA[kk * B + bb];
        else if (kk < KX) v = srcB[(kk - WA) * B + bb];
        else v = hprev[(kk - KX) * B + bb];
        s.xs[0][kk][bb] = v;
    }
    __syncthreads();
    for (int c = 0; c < NC; ++c) {
        const int k0 = c * 64;
        const float* wr = (k0 < KX) ? (wihr + k0) : (whhr + (k0 - KX));
        float4 w[16];
#pragma unroll
        for (int q = 0; q < 16; ++q) w[q] = __ldg((const float4*)wr + q);
        float xr[8];
        if (c + 1 < NC) {
            const int k0n = k0 + 64;
#pragma unroll
            for (int i = 0; i < 8; ++i) {
                int idx = tid + i * 256;
                int kk = idx >> 5, bb = idx & 31;
                int k = k0n + kk;
                float v;
                if (k < WA) v = srcA[k * B + bb];
                else if (k < KX) v = srcB[(k - WA) * B + bb];
                else v = hprev[(k - KX) * B + bb];
                xr[i] = v;
            }
        }
        const float (*xb)[B] = s.xs[c & 1];
#pragma unroll
        for (int q = 0; q < 16; ++q) {
            float4 wv = w[q];
            float4 x;
            x = *(const float4*)&xb[q * 4 + 0][bg * 4];
            a0 += wv.x * x.x; a1 += wv.x * x.y; a2 += wv.x * x.z; a3 += wv.x * x.w;
            x = *(const float4*)&xb[q * 4 + 1][bg * 4];
            a0 += wv.y * x.x; a1 += wv.y * x.y; a2 += wv.y * x.z; a3 += wv.y * x.w;
            x = *(const float4*)&xb[q * 4 + 2][bg * 4];
            a0 += wv.z * x.x; a1 += wv.z * x.y; a2 += wv.z * x.z; a3 += wv.z * x.w;
            x = *(const float4*)&xb[q * 4 + 3][bg * 4];
            a0 += wv.w * x.x; a1 += wv.w * x.y; a2 += wv.w * x.z; a3 += wv.w * x.w;
        }
        if (c + 1 < NC) {
#pragma unroll
            for (int i = 0; i < 8; ++i) {
                int idx = tid + i * 256;
                s.xs[(c + 1) & 1][idx >> 5][idx & 31] = xr[i];
            }
        }
        __syncthreads();
    }
    float bias = bih[j] + bhh[j];
    s.zs[gg][hh][bg * 4 + 0] = a0 + bias;
    s.zs[gg][hh][bg * 4 + 1] = a1 + bias;
    s.zs[gg][hh][bg * 4 + 2] = a2 + bias;
    s.zs[gg][hh][bg * 4 + 3] = a3 + bias;
    __syncthreads();
    const int b2 = tid & 31, hh2 = tid >> 5;
    const int h = h0 + hh2;
    float zi = s.zs[0][hh2][b2], zf = s.zs[1][hh2][b2];
    float zg = s.zs[2][hh2][b2], zo = s.zs[3][hh2][b2];
    float c = cst[h * B + b2];
    float cn = sigf(zf) * c + sigf(zi) * tanhf(zg);
    cst[h * B + b2] = cn;
    float hv = sigf(zo) * tanhf(cn);
    hout[h * B + b2] = hv;
    houtbm[b2 * 1024 + h] = hv;
}

// ---------------- fused attention: pq + conv + energies + softmax + context ----------
// one block per batch element (blocks 0..31)
__device__ void attn_phase(const float* __restrict__ qw, const float* __restrict__ convw,
                           const float* __restrict__ loclin, const float* __restrict__ vw,
                           const int* __restrict__ lens, const float* __restrict__ memory,
                           int t, int cur, float* __restrict__ out_align, SAtt& s) {
    const int b = blockIdx.x, tid = threadIdx.x;
    const int warp = tid >> 5, lane = tid & 31;
    // loads
    ((float4*)s.ahs)[tid] = ((const float4*)&g_ahbm[cur][b * ARNN])[tid];
    for (int i = tid; i < TIN + 30; i += 256) {
        int tp = i - 15;
        bool ok = (tp >= 0 && tp < TIN);
        s.cat0[i] = ok ? g_aw[b * TIN + tp] : 0.f;
        s.cat1[i] = ok ? g_awc[b * TIN + tp] : 0.f;
    }
    for (int i = tid; i < 62 * LOCF; i += 256) s.cwsT[i >> 5][i & 31] = convw[(i & 31) * 62 + (i >> 5)];
    for (int i = tid; i < ATT * LOCF; i += 256) s.lls[i] = loclin[i];
    if (tid < ATT) s.vs[tid] = vw[tid];
    __syncthreads();
    // pq: warp computes 16 rows
#pragma unroll 1
    for (int r = 0; r < 16; ++r) {
        int a = warp * 16 + r;
        const float4* w = (const float4*)(qw + (size_t)a * ARNN);
        const float4* hv = (const float4*)s.ahs;
        float acc = 0.f;
#pragma unroll
        for (int i = 0; i < 8; ++i) {
            float4 wv = __ldg(&w[lane + i * 32]);
            float4 xv = hv[lane + i * 32];
            acc += wv.x * xv.x + wv.y * xv.y + wv.z * xv.z + wv.w * xv.w;
        }
        acc = wsum(acc);
        if (lane == 0) s.pqs[a] = acc;
    }
    __syncthreads();
    // energies: 2 passes, tp = tid + pass*256
    float epass[2];
    const int len = lens[b];
#pragma unroll 1
    for (int pass = 0; pass < 2; ++pass) {
        const int tp = tid + pass * 256;
        float lf[LOCF];
#pragma unroll
        for (int f = 0; f < LOCF; ++f) lf[f] = 0.f;
#pragma unroll 2
        for (int kc = 0; kc < 62; ++kc) {
            float cv = (kc < 31) ? s.cat0[tp + kc] : s.cat1[tp + kc - 31];
            const float4* w = (const float4*)&s.cwsT[kc][0];
#pragma unroll
            for (int i = 0; i < 8; ++i) {
                float4 wv = w[i];
                lf[i * 4 + 0] += cv * wv.x; lf[i * 4 + 1] += cv * wv.y;
                lf[i * 4 + 2] += cv * wv.z; lf[i * 4 + 3] += cv * wv.w;
            }
        }
        const float* pm = g_pmemT + (size_t)b * ATT * TIN + tp;
        float en = 0.f;
#pragma unroll 4
        for (int a = 0; a < ATT; ++a) {
            float s0 = s.pqs[a] + __ldg(&pm[(size_t)a * TIN]);
            const float4* ll = (const float4*)&s.lls[a * LOCF];
#pragma unroll
            for (int i = 0; i < 8; ++i) {
                float4 lv = ll[i];
                s0 += lv.x * lf[i * 4] + lv.y * lf[i * 4 + 1] + lv.z * lf[i * 4 + 2] + lv.w * lf[i * 4 + 3];
            }
            en += s.vs[a] * tanha(s0);
        }
        if (tp >= len) en = -1e9f;
        epass[pass] = en;
    }
    // softmax over 512
    float m = fmaxf(epass[0], epass[1]);
    m = wmax(m);
    if (lane == 0) s.red[warp] = m;
    __syncthreads();
    if (tid < 32) {
        float mm = (lane < 8) ? s.red[lane] : -3.4e38f;
        mm = wmax(mm);
        if (lane == 0) s.red[0] = mm;
    }
    __syncthreads();
    m = s.red[0];
    float p0 = __expf(epass[0] - m), p1 = __expf(epass[1] - m);
    float ps = p0 + p1;
    ps = wsum(ps);
    __syncthreads();
    if (lane == 0) s.red[warp] = ps;
    __syncthreads();
    if (tid < 32) {
        float ss = (lane < 8) ? s.red[lane] : 0.f;
        ss = wsum(ss);
        if (lane == 0) s.red[0] = ss;
    }
    __syncthreads();
    float inv = __fdividef(1.f, s.red[0]);
    float a0 = p0 * inv, a1 = p1 * inv;
    s.sw[tid] = a0; s.sw[tid + 256] = a1;
    g_aw[b * TIN + tid] = a0; g_aw[b * TIN + tid + 256] = a1;
    g_awc[b * TIN + tid] += a0; g_awc[b * TIN + tid + 256] += a1;
    float* oa = out_align + ((size_t)b * TOUT + t) * TIN;
    oa[tid] = a0; oa[tid + 256] = a1;
    __syncthreads();
    // context: d = tid and tid+256
    const float* mb = memory + (size_t)b * TIN * ENC + tid;
    float acc0 = 0.f, acc1 = 0.f;
#pragma unroll 4
    for (int tt = 0; tt < TIN; ++tt) {
        float w = s.sw[tt];
        acc0 += w * __ldg(&mb[(size_t)tt * ENC]);
        acc1 += w * __ldg(&mb[(size_t)tt * ENC + 256]);
    }
    g_actx[tid * B + b] = acc0;
    g_actx[(tid + 256) * B + b] = acc1;
    g_actxbm[b * ENC + tid] = acc0;
    g_actxbm[b * ENC + tid + 256] = acc1;
}

// ---------------- projection + gate (blocks < 32) ----------------
__device__ void proj_phase(const float* __restrict__ pw, const float* __restrict__ pb,
                           const float* __restrict__ gw, const float* __restrict__ gb,
                           int t, int cur, float* __restrict__ out_mel,
                           float* __restrict__ out_gate, SProj& s) {
    const int b = blockIdx.x, tid = threadIdx.x;
    const int warp = tid >> 5, lane = tid & 31;
    for (int i = tid; i < DRNN; i += 256) s.sd[i] = g_dhbm[cur][b * DRNN + i];
    for (int i = tid; i < ENC; i += 256) s.sd[DRNN + i] = g_actxbm[b * ENC + i];
    __syncthreads();
    for (int r = warp; r < NMEL + 1; r += 8) {
        const float4* w = (const float4*)((r < NMEL) ? (pw + (size_t)r * (DRNN + ENC)) : gw);
        const float4* x = (const float4*)s.sd;
        float acc = 0.f;
#pragma unroll
        for (int i = 0; i < 12; ++i) {
            float4 wv = __ldg(&w[lane + i * 32]);
            float4 xv = x[lane + i * 32];
            acc += wv.x * xv.x + wv.y * xv.y + wv.z * xv.z + wv.w * xv.w;
        }
        acc = wsum(acc);
        if (lane == 0) {
            if (r < NMEL) out_mel[(size_t)b * NMEL * TOUT + (size_t)r * TOUT + t] = acc + pb[r];
            else out_gate[(size_t)b * TOUT + t] = acc + gb[0];
        }
    }
    __syncthreads();
}

// ---------------- persistent decoder ----------------
__global__ __launch_bounds__(256, 1)
void persist_kernel(const float* __restrict__ memory,
                    const float* __restrict__ awih, const float* __restrict__ awhh,
                    const float* __restrict__ abih, const float* __restrict__ abhh,
                    const float* __restrict__ qw, const float* __restrict__ vw,
                    const float* __restrict__ convw, const float* __restrict__ loclin,
                    const float* __restrict__ dwih, const float* __restrict__ dwhh,
                    const float* __restrict__ dbih, const float* __restrict__ dbhh,
                    const float* __restrict__ pw, const float* __restrict__ pb,
                    const float* __restrict__ gw, const float* __restrict__ gb,
                    const int* __restrict__ lens,
                    float* __restrict__ out_mel, float* __restrict__ out_gate,
                    float* __restrict__ out_align) {
    __shared__ Smem sm;
    for (int t = 0; t < TOUT; ++t) {
        const int cur = t & 1, prev = cur ^ 1;
        lstm_phase<PRE, ENC>(g_pren + (size_t)t * PRE * B, g_actx, &g_ah[prev][0],
                             awih, awhh, abih, abhh, g_ac, &g_ah[cur][0], &g_ahbm[cur][0], sm.l);
        gbar();
        if (blockIdx.x < 32)
            attn_phase(qw, convw, loclin, vw, lens, memory, t, cur, out_align, sm.a);
        gbar();
        lstm_phase<ARNN, ENC>(&g_ah[cur][0], g_actx, &g_dh[prev][0],
                              dwih, dwhh, dbih, dbhh, g_dc, &g_dh[cur][0], &g_dhbm[cur][0], sm.l);
        gbar();
        if (blockIdx.x < 32)
            proj_phase(pw, pb, gw, gb, t, cur, out_mel, out_gate, sm.p);
        // proj(t) overlaps attLSTM(t+1): disjoint buffers, ordered by next gbar
    }
}

// ---------------- launch ----------------
extern "C" void kernel_launch(void* const* d_in, const int* in_sizes, int n_in,
                              void* d_out, int out_size) {
    const float* memory = (const float*)d_in[0];
    const float* dec    = (const float*)d_in[1];
    const float* w1     = (const float*)d_in[2];
    const float* w2     = (const float*)d_in[3];
    const float* awih   = (const float*)d_in[4];
    const float* awhh   = (const float*)d_in[5];
    const float* abih   = (const float*)d_in[6];
    const float* abhh   = (const float*)d_in[7];
    const float* qw     = (const float*)d_in[8];
    const float* memw   = (const float*)d_in[9];
    const float* vw     = (const float*)d_in[10];
    const float* convw  = (const float*)d_in[11];
    const float* loclin = (const float*)d_in[12];
    const float* dwih   = (const float*)d_in[13];
    const float* dwhh   = (const float*)d_in[14];
    const float* dbih   = (const float*)d_in[15];
    const float* dbhh   = (const float*)d_in[16];
    const float* pw     = (const float*)d_in[17];
    const float* pb     = (const float*)d_in[18];
    const float* gw     = (const float*)d_in[19];
    const float* gb     = (const float*)d_in[20];
    const int*   lens   = (const int*)d_in[21];

    float* out_mel = (float*)d_out;
    float* out_gate = out_mel + (size_t)B * NMEL * TOUT;
    float* out_align = out_gate + (size_t)B * TOUT;

    zero_kernel<<<(ARNN * B + 255) / 256, 256>>>();
    prenet_kernel<<<TOUT * B, 256>>>(dec, w1, w2);
    pmem_kernel<<<dim3(B, TIN / 16), 128>>>(memory, memw);
    persist_kernel<<<NB, 256>>>(memory, awih, awhh, abih, abhh, qw, vw, convw, loclin,
                                dwih, dwhh, dbih, dbhh, pw, pb, gw, gb, lens,
                                out_mel, out_gate, out_align);
}

// round 5
// speedup vs baseline: 1.6892x; 1.1323x over previous
#include <cuda_runtime.h>
#include <math.h>

#define B 32
#define TIN 512
#define TOUT 800
#define NMEL 80
#define ENC 512
#define ARNN 1024
#define DRNN 1024
#define PRE 256
#define ATT 128
#define LOCF 32
#define LOCK 31
#define NB 256

// ---------------- device state ----------------
static __device__ float g_pren[(size_t)TOUT * PRE * B];   // [t][j][b]
static __device__ float g_pmemT[(size_t)B * ATT * TIN];   // [b][a][t]
static __device__ float g_ah[2][ARNN * B];                // [h][b]
static __device__ float g_ahbm[2][B * ARNN];              // [b][h]
static __device__ float g_ac[ARNN * B];
static __device__ float g_dh[2][DRNN * B];
static __device__ float g_dhbm[2][B * DRNN];
static __device__ float g_dc[DRNN * B];
static __device__ float g_aw[B * TIN];
static __device__ float g_awc[B * TIN];
static __device__ float g_actx[ENC * B];                  // [d][b]
static __device__ float g_actxbm[B * ENC];                // [b][d]
static __device__ float g_energy[B * TIN];
static __device__ __align__(128) unsigned g_count;
static __device__ __align__(128) volatile unsigned g_epoch;

__device__ __forceinline__ float sigf(float x) { return __fdividef(1.f, 1.f + __expf(-x)); }
__device__ __forceinline__ float tanha(float x) {
    float y; asm("tanh.approx.f32 %0, %1;" : "=f"(y) : "f"(x)); return y;
}
__device__ __forceinline__ float wsum(float v) {
#pragma unroll
    for (int o = 16; o > 0; o >>= 1) v += __shfl_xor_sync(0xffffffffu, v, o);
    return v;
}
__device__ __forceinline__ float wmax(float v) {
#pragma unroll
    for (int o = 16; o > 0; o >>= 1) v = fmaxf(v, __shfl_xor_sync(0xffffffffu, v, o));
    return v;
}

// ---------------- grid barrier ----------------
__device__ __forceinline__ void gbar() {
    __syncthreads();
    if (threadIdx.x == 0) {
        unsigned e = g_epoch;
        __threadfence();
        if (atomicAdd(&g_count, 1) == NB - 1) {
            g_count = 0;
            __threadfence();
            g_epoch = e + 1;
        } else {
            while (g_epoch == e) __nanosleep(64);
        }
        __threadfence();
    }
    __syncthreads();
}

// ---------------- shared memory ----------------
struct SLstm { float xs[2][64][B]; float zs[4][4][B]; };
struct SAtt {
    float ahs[ARNN];
    float pqs[ATT]; float vs[ATT];
    float cat0[158]; float cat1[158];
    float cwsT[62][LOCF];
    float lls[ATT * LOCF];
    float lfs[128][LOCF + 1];
    float ep[256];
};
struct SSoft { float sw[TIN]; float red[8]; };
struct SProj { float sd[DRNN + ENC]; };
union Smem { SLstm l; SAtt a; SSoft s; SProj p; };

// ---------------- init ----------------
__global__ void zero_kernel() {
    int i = blockIdx.x * blockDim.x + threadIdx.x;
    if (i < ARNN * B) {
        g_ah[0][i] = 0.f; g_ah[1][i] = 0.f; g_ahbm[0][i] = 0.f; g_ahbm[1][i] = 0.f; g_ac[i] = 0.f;
        g_dh[0][i] = 0.f; g_dh[1][i] = 0.f; g_dhbm[0][i] = 0.f; g_dhbm[1][i] = 0.f; g_dc[i] = 0.f;
    }
    if (i < B * TIN) { g_aw[i] = 0.f; g_awc[i] = 0.f; }
    if (i < ENC * B) { g_actx[i] = 0.f; }
    if (i == 0) { g_count = 0; g_epoch = 0; }
}

// ---------------- prenet precompute -> g_pren[t][j][b] ----------------
__global__ __launch_bounds__(256)
void prenet_kernel(const float* __restrict__ dec, const float* __restrict__ w1,
                   const float* __restrict__ w2) {
    int t = blockIdx.x >> 5;
    int b = blockIdx.x & 31;
    int tid = threadIdx.x;
    __shared__ float xm[NMEL];
    __shared__ float x1[PRE];
    if (tid < NMEL)
        xm[tid] = (t == 0) ? 0.f : dec[(size_t)b * NMEL * TOUT + (size_t)tid * TOUT + (t - 1)];
    __syncthreads();
    {
        const float* w = w1 + tid * NMEL;
        float s = 0.f;
#pragma unroll
        for (int m = 0; m < NMEL; ++m) s += xm[m] * w[m];
        x1[tid] = fmaxf(s, 0.f);
    }
    __syncthreads();
    {
        const float* w = w2 + tid * PRE;
        float s = 0.f;
#pragma unroll 8
        for (int k = 0; k < PRE; ++k) s += x1[k] * w[k];
        g_pren[((size_t)t * PRE + tid) * B + b] = fmaxf(s, 0.f);
    }
}

// ---------------- pmemT precompute -> [b][a][t] ----------------
__global__ __launch_bounds__(128)
void pmem_kernel(const float* __restrict__ memory, const float* __restrict__ memw) {
    int b = blockIdx.x;
    int tb = blockIdx.y * 16;
    int a = threadIdx.x;
    __shared__ __align__(16) float xs[64][16];
    __shared__ float ws[128 * 65];
    float acc[16];
#pragma unroll
    for (int i = 0; i < 16; ++i) acc[i] = 0.f;
    for (int e0 = 0; e0 < ENC; e0 += 64) {
        __syncthreads();
#pragma unroll
        for (int i2 = 0; i2 < 8; ++i2) {
            int idx = a + i2 * 128;
            int ee = idx & 63, tt = idx >> 6;
            xs[ee][tt] = memory[(size_t)b * TIN * ENC + (size_t)(tb + tt) * ENC + e0 + ee];
        }
#pragma unroll
        for (int i2 = 0; i2 < 64; ++i2) {
            int idx = a + i2 * 128;
            int ee = idx & 63, aa = idx >> 6;
            ws[aa * 65 + ee] = memw[aa * ENC + e0 + ee];
        }
        __syncthreads();
#pragma unroll 4
        for (int ee = 0; ee < 64; ++ee) {
            float w = ws[a * 65 + ee];
            const float4* xr = (const float4*)&xs[ee][0];
            float4 v0 = xr[0], v1 = xr[1], v2 = xr[2], v3 = xr[3];
            acc[0] += w * v0.x; acc[1] += w * v0.y; acc[2] += w * v0.z; acc[3] += w * v0.w;
            acc[4] += w * v1.x; acc[5] += w * v1.y; acc[6] += w * v1.z; acc[7] += w * v1.w;
            acc[8] += w * v2.x; acc[9] += w * v2.y; acc[10] += w * v2.z; acc[11] += w * v2.w;
            acc[12] += w * v3.x; acc[13] += w * v3.y; acc[14] += w * v3.z; acc[15] += w * v3.w;
        }
    }
    float* o = g_pmemT + (size_t)b * ATT * TIN + (size_t)a * TIN + tb;
#pragma unroll
    for (int i = 0; i < 16; ++i) o[i] = acc[i];
}

// ---------------- LSTM phase: 4 h per block, 16 rows x 16 subs, 2 batches/thread ----
template <int WA, int WB>
__device__ void lstm_phase(const float* __restrict__ srcA, const float* __restrict__ srcB,
                           const float* __restrict__ hprev,
                           const float* __restrict__ wih, const float* __restrict__ whh,
                           const float* __restrict__ bih, const float* __restrict__ bhh,
                           float* __restrict__ cst, float* __restrict__ hout,
                           float* __restrict__ houtbm, SLstm& s) {
    constexpr int KX = WA + WB;
    constexpr int KTOT = KX + 1024;
    constexpr int NC = KTOT / 64;
    const int tid = threadIdx.x;
    const int row = tid >> 4;          // 0..15
    const int sub = tid & 15;          // batches 2*sub, 2*sub+1
    const int gg = row >> 2, hh = row & 3;
    const int h0 = blockIdx.x * 4;
    const int j = gg * 1024 + h0 + hh;
    const float* wihr = wih + (size_t)j * KX;
    const float* whhr = whh + (size_t)j * 1024;
    float a0 = 0.f, a1 = 0.f;
    // stage chunk 0
#pragma unroll
    for (int i = 0; i < 8; ++i) {
        int idx = tid + i * 256;
        int kk = idx >> 5, bb = idx & 31;
        float v;
        if (kk < WA) v = srcA[kk * B + bb];
        else if (kk < KX) v = srcB[(kk - WA) * B + bb];
        else v = hprev[(kk - KX) * B + bb];
        s.xs[0][kk][bb] = v;
    }
    __syncthreads();
    for (int c = 0; c < NC; ++c) {
        const int k0 = c * 64;
        const float* wr = (k0 < KX) ? (wihr + k0) : (whhr + (k0 - KX));
        float4 w[16];
#pragma unroll
        for (int q = 0; q < 16; ++q) w[q] = __ldg((const float4*)wr + q);
        float xr[8];
        if (c + 1 < NC) {
            const int k0n = k0 + 64;
#pragma unroll
            for (int i = 0; i < 8; ++i) {
                int idx = tid + i * 256;
                int kk = idx >> 5, bb = idx & 31;
                int k = k0n + kk;
                float v;
                if (k < WA) v = srcA[k * B + bb];
                else if (k < KX) v = srcB[(k - WA) * B + bb];
                else v = hprev[(k - KX) * B + bb];
                xr[i] = v;
            }
        }
        const float (*xb)[B] = s.xs[c & 1];
#pragma unroll
        for (int q = 0; q < 16; ++q) {
            float4 wv = w[q];
            float2 x;
            x = *(const float2*)&xb[q * 4 + 0][sub * 2];
            a0 += wv.x * x.x; a1 += wv.x * x.y;
            x = *(const float2*)&xb[q * 4 + 1][sub * 2];
            a0 += wv.y * x.x; a1 += wv.y * x.y;
            x = *(const float2*)&xb[q * 4 + 2][sub * 2];
            a0 += wv.z * x.x; a1 += wv.z * x.y;
            x = *(const float2*)&xb[q * 4 + 3][sub * 2];
            a0 += wv.w * x.x; a1 += wv.w * x.y;
        }
        if (c + 1 < NC) {
#pragma unroll
            for (int i = 0; i < 8; ++i) {
                int idx = tid + i * 256;
                s.xs[(c + 1) & 1][idx >> 5][idx & 31] = xr[i];
            }
        }
        __syncthreads();
    }
    float bias = bih[j] + bhh[j];
    s.zs[gg][hh][sub * 2] = a0 + bias;
    s.zs[gg][hh][sub * 2 + 1] = a1 + bias;
    __syncthreads();
    if (tid < 128) {
        const int b2 = tid & 31, hh2 = tid >> 5;   // 0..3
        const int h = h0 + hh2;
        float zi = s.zs[0][hh2][b2], zf = s.zs[1][hh2][b2];
        float zg = s.zs[2][hh2][b2], zo = s.zs[3][hh2][b2];
        float c = cst[h * B + b2];
        float cn = sigf(zf) * c + sigf(zi) * tanhf(zg);
        cst[h * B + b2] = cn;
        float hv = sigf(zo) * tanhf(cn);
        hout[h * B + b2] = hv;
        houtbm[b2 * 1024 + h] = hv;
    }
}

// ---------------- energy phase: 128 blocks, 4 per batch, 128 t each ----------------
__device__ void energy_phase(const float* __restrict__ qw, const float* __restrict__ convw,
                             const float* __restrict__ loclin, const float* __restrict__ vw,
                             const int* __restrict__ lens, int cur, SAtt& s) {
    const int blk = blockIdx.x;
    const int b = blk >> 2;
    const int tbase = (blk & 3) * 128;
    const int tid = threadIdx.x, warp = tid >> 5, lane = tid & 31;
    ((float4*)s.ahs)[tid] = ((const float4*)&g_ahbm[cur][b * ARNN])[tid];
    for (int i = tid; i < 158; i += 256) {
        int tp = tbase - 15 + i;
        bool ok = (tp >= 0 && tp < TIN);
        s.cat0[i] = ok ? g_aw[b * TIN + tp] : 0.f;
        s.cat1[i] = ok ? g_awc[b * TIN + tp] : 0.f;
    }
    for (int i = tid; i < 62 * LOCF; i += 256) s.cwsT[i >> 5][i & 31] = convw[(i & 31) * 62 + (i >> 5)];
    for (int i = tid; i < ATT * LOCF; i += 256) s.lls[i] = loclin[i];
    if (tid < ATT) s.vs[tid] = vw[tid];
    __syncthreads();
    // pq: 8 warps x 16 rows (recomputed per block; tiny)
#pragma unroll 1
    for (int r = 0; r < 16; ++r) {
        int a = warp * 16 + r;
        const float4* w = (const float4*)(qw + (size_t)a * ARNN);
        const float4* hv = (const float4*)s.ahs;
        float acc = 0.f;
#pragma unroll
        for (int i = 0; i < 8; ++i) {
            float4 wv = __ldg(&w[lane + i * 32]);
            float4 xv = hv[lane + i * 32];
            acc += wv.x * xv.x + wv.y * xv.y + wv.z * xv.z + wv.w * xv.w;
        }
        acc = wsum(acc);
        if (lane == 0) s.pqs[a] = acc;
    }
    // conv: t = tid&127, half = tid>>7 computes 16 filters
    {
        const int t = tid & 127, hf = tid >> 7;
        float lf[16];
#pragma unroll
        for (int i = 0; i < 16; ++i) lf[i] = 0.f;
#pragma unroll 2
        for (int kc = 0; kc < 62; ++kc) {
            float cv = (kc < 31) ? s.cat0[t + kc] : s.cat1[t + kc - 31];
            const float4* w = (const float4*)&s.cwsT[kc][hf * 16];
            float4 w0 = w[0], w1 = w[1], w2 = w[2], w3 = w[3];
            lf[0] += cv * w0.x; lf[1] += cv * w0.y; lf[2] += cv * w0.z; lf[3] += cv * w0.w;
            lf[4] += cv * w1.x; lf[5] += cv * w1.y; lf[6] += cv * w1.z; lf[7] += cv * w1.w;
            lf[8] += cv * w2.x; lf[9] += cv * w2.y; lf[10] += cv * w2.z; lf[11] += cv * w2.w;
            lf[12] += cv * w3.x; lf[13] += cv * w3.y; lf[14] += cv * w3.z; lf[15] += cv * w3.w;
        }
#pragma unroll
        for (int i = 0; i < 16; ++i) s.lfs[t][hf * 16 + i] = lf[i];
    }
    __syncthreads();
    // energies: t = tid&127, a-half = tid>>7 (64 dims each)
    {
        const int t = tid & 127, ah = tid >> 7;
        float lfr[32];
#pragma unroll
        for (int i = 0; i < 32; ++i) lfr[i] = s.lfs[t][i];
        const float* pm = g_pmemT + (size_t)b * ATT * TIN + tbase + t;
        float e = 0.f;
#pragma unroll 2
        for (int a = ah * 64; a < ah * 64 + 64; ++a) {
            float s0 = s.pqs[a] + __ldg(&pm[(size_t)a * TIN]);
            const float4* ll = (const float4*)&s.lls[a * LOCF];
#pragma unroll
            for (int i = 0; i < 8; ++i) {
                float4 lv = ll[i];
                s0 += lv.x * lfr[i * 4] + lv.y * lfr[i * 4 + 1] + lv.z * lfr[i * 4 + 2] + lv.w * lfr[i * 4 + 3];
            }
            e += s.vs[a] * tanha(s0);
        }
        s.ep[tid] = e;
    }
    __syncthreads();
    if (tid < 128) {
        int tp = tbase + tid;
        float e = s.ep[tid] + s.ep[tid + 128];
        if (tp >= lens[b]) e = -1e9f;
        g_energy[b * TIN + tp] = e;
    }
}

// ---------------- softmax + context (blocks < 32) ----------------
__device__ void softctx_phase(const float* __restrict__ memory, int t,
                              float* __restrict__ out_align, SSoft& s) {
    const int b = blockIdx.x, tid = threadIdx.x;
    const int warp = tid >> 5, lane = tid & 31;
    float e0 = g_energy[b * TIN + tid];
    float e1 = g_energy[b * TIN + tid + 256];
    float m = fmaxf(e0, e1);
    m = wmax(m);
    if (lane == 0) s.red[warp] = m;
    __syncthreads();
    if (tid < 32) {
        float mm = (lane < 8) ? s.red[lane] : -3.4e38f;
        mm = wmax(mm);
        if (lane == 0) s.red[0] = mm;
    }
    __syncthreads();
    m = s.red[0];
    float p0 = __expf(e0 - m), p1 = __expf(e1 - m);
    float ps = wsum(p0 + p1);
    __syncthreads();
    if (lane == 0) s.red[warp] = ps;
    __syncthreads();
    if (tid < 32) {
        float ss = (lane < 8) ? s.red[lane] : 0.f;
        ss = wsum(ss);
        if (lane == 0) s.red[0] = ss;
    }
    __syncthreads();
    float inv = __fdividef(1.f, s.red[0]);
    float a0 = p0 * inv, a1 = p1 * inv;
    s.sw[tid] = a0; s.sw[tid + 256] = a1;
    g_aw[b * TIN + tid] = a0; g_aw[b * TIN + tid + 256] = a1;
    g_awc[b * TIN + tid] += a0; g_awc[b * TIN + tid + 256] += a1;
    float* oa = out_align + ((size_t)b * TOUT + t) * TIN;
    oa[tid] = a0; oa[tid + 256] = a1;
    __syncthreads();
    const float* mb = memory + (size_t)b * TIN * ENC + tid;
    float c0 = 0.f, c1 = 0.f;
#pragma unroll 4
    for (int tt = 0; tt < TIN; ++tt) {
        float w = s.sw[tt];
        c0 += w * __ldg(&mb[(size_t)tt * ENC]);
        c1 += w * __ldg(&mb[(size_t)tt * ENC + 256]);
    }
    g_actx[tid * B + b] = c0;
    g_actx[(tid + 256) * B + b] = c1;
    g_actxbm[b * ENC + tid] = c0;
    g_actxbm[b * ENC + tid + 256] = c1;
}

// ---------------- projection + gate (blocks < 32) ----------------
__device__ void proj_phase(const float* __restrict__ pw, const float* __restrict__ pb,
                           const float* __restrict__ gw, const float* __restrict__ gb,
                           int t, int cur, float* __restrict__ out_mel,
                           float* __restrict__ out_gate, SProj& s) {
    const int b = blockIdx.x, tid = threadIdx.x;
    const int warp = tid >> 5, lane = tid & 31;
    for (int i = tid; i < DRNN; i += 256) s.sd[i] = g_dhbm[cur][b * DRNN + i];
    for (int i = tid; i < ENC; i += 256) s.sd[DRNN + i] = g_actxbm[b * ENC + i];
    __syncthreads();
    for (int r = warp; r < NMEL + 1; r += 8) {
        const float4* w = (const float4*)((r < NMEL) ? (pw + (size_t)r * (DRNN + ENC)) : gw);
        const float4* x = (const float4*)s.sd;
        float acc = 0.f;
#pragma unroll
        for (int i = 0; i < 12; ++i) {
            float4 wv = __ldg(&w[lane + i * 32]);
            float4 xv = x[lane + i * 32];
            acc += wv.x * xv.x + wv.y * xv.y + wv.z * xv.z + wv.w * xv.w;
        }
        acc = wsum(acc);
        if (lane == 0) {
            if (r < NMEL) out_mel[(size_t)b * NMEL * TOUT + (size_t)r * TOUT + t] = acc + pb[r];
            else out_gate[(size_t)b * TOUT + t] = acc + gb[0];
        }
    }
    __syncthreads();
}

// ---------------- persistent decoder ----------------
__global__ __launch_bounds__(256, 2)
void persist_kernel(const float* __restrict__ memory,
                    const float* __restrict__ awih, const float* __restrict__ awhh,
                    const float* __restrict__ abih, const float* __restrict__ abhh,
                    const float* __restrict__ qw, const float* __restrict__ vw,
                    const float* __restrict__ convw, const float* __restrict__ loclin,
                    const float* __restrict__ dwih, const float* __restrict__ dwhh,
                    const float* __restrict__ dbih, const float* __restrict__ dbhh,
                    const float* __restrict__ pw, const float* __restrict__ pb,
                    const float* __restrict__ gw, const float* __restrict__ gb,
                    const int* __restrict__ lens,
                    float* __restrict__ out_mel, float* __restrict__ out_gate,
                    float* __restrict__ out_align) {
    extern __shared__ __align__(16) char smraw[];
    Smem& sm = *reinterpret_cast<Smem*>(smraw);
    for (int t = 0; t < TOUT; ++t) {
        const int cur = t & 1, prev = cur ^ 1;
        lstm_phase<PRE, ENC>(g_pren + (size_t)t * PRE * B, g_actx, &g_ah[prev][0],
                             awih, awhh, abih, abhh, g_ac, &g_ah[cur][0], &g_ahbm[cur][0], sm.l);
        gbar();
        if (blockIdx.x < 128)
            energy_phase(qw, convw, loclin, vw, lens, cur, sm.a);
        gbar();
        if (blockIdx.x < 32)
            softctx_phase(memory, t, out_align, sm.s);
        gbar();
        lstm_phase<ARNN, ENC>(&g_ah[cur][0], g_actx, &g_dh[prev][0],
                              dwih, dwhh, dbih, dbhh, g_dc, &g_dh[cur][0], &g_dhbm[cur][0], sm.l);
        gbar();
        if (blockIdx.x < 32)
            proj_phase(pw, pb, gw, gb, t, cur, out_mel, out_gate, sm.p);
        // proj(t) overlaps attLSTM(t+1): disjoint buffers, ordered by barriers
    }
}

// ---------------- launch ----------------
extern "C" void kernel_launch(void* const* d_in, const int* in_sizes, int n_in,
                              void* d_out, int out_size) {
    const float* memory = (const float*)d_in[0];
    const float* dec    = (const float*)d_in[1];
    const float* w1     = (const float*)d_in[2];
    const float* w2     = (const float*)d_in[3];
    const float* awih   = (const float*)d_in[4];
    const float* awhh   = (const float*)d_in[5];
    const float* abih   = (const float*)d_in[6];
    const float* abhh   = (const float*)d_in[7];
    const float* qw     = (const float*)d_in[8];
    const float* memw   = (const float*)d_in[9];
    const float* vw     = (const float*)d_in[10];
    const float* convw  = (const float*)d_in[11];
    const float* loclin = (const float*)d_in[12];
    const float* dwih   = (const float*)d_in[13];
    const float* dwhh   = (const float*)d_in[14];
    const float* dbih   = (const float*)d_in[15];
    const float* dbhh   = (const float*)d_in[16];
    const float* pw     = (const float*)d_in[17];
    const float* pb     = (const float*)d_in[18];
    const float* gw     = (const float*)d_in[19];
    const float* gb     = (const float*)d_in[20];
    const int*   lens   = (const int*)d_in[21];

    float* out_mel = (float*)d_out;
    float* out_gate = out_mel + (size_t)B * NMEL * TOUT;
    float* out_align = out_gate + (size_t)B * TOUT;

    cudaFuncSetAttribute(persist_kernel, cudaFuncAttributeMaxDynamicSharedMemorySize,
                         (int)sizeof(Smem));

    zero_kernel<<<(ARNN * B + 255) / 256, 256>>>();
    prenet_kernel<<<TOUT * B, 256>>>(dec, w1, w2);
    pmem_kernel<<<dim3(B, TIN / 16), 128>>>(memory, memw);
    persist_kernel<<<NB, 256, sizeof(Smem)>>>(memory, awih, awhh, abih, abhh, qw, vw,
                                              convw, loclin, dwih, dwhh, dbih, dbhh,
                                              pw, pb, gw, gb, lens,
                                              out_mel, out_gate, out_align);
}

// round 6
// speedup vs baseline: 2.0753x; 1.2286x over previous
#include <cuda_runtime.h>
#include <math.h>

#define B 32
#define TIN 512
#define TOUT 800
#define NMEL 80
#define ENC 512
#define ARNN 1024
#define DRNN 1024
#define PRE 256
#define ATT 128
#define LOCF 32
#define LOCK 31
#define NB 256

// ---------------- device state ----------------
static __device__ float g_pren[(size_t)TOUT * PRE * B];   // [t][j][b]
static __device__ float g_pmemT[(size_t)B * ATT * TIN];   // [b][a][t]
static __device__ float g_zpart[4 * 4096 * B];            // [ks][j][b] partial gate sums
static __device__ float g_ah[2][ARNN * B];                // [h][b]
static __device__ float g_ahbm[2][B * ARNN];              // [b][h]
static __device__ float g_ac[ARNN * B];
static __device__ float g_dh[2][DRNN * B];
static __device__ float g_dhbm[2][B * DRNN];
static __device__ float g_dc[DRNN * B];
static __device__ float g_aw[B * TIN];
static __device__ float g_awc[B * TIN];
static __device__ float g_actx[ENC * B];                  // [d][b]
static __device__ float g_actxbm[B * ENC];                // [b][d]
static __device__ float g_energy[B * TIN];
static __device__ __align__(128) unsigned g_count;
static __device__ __align__(128) volatile unsigned g_epoch;

__device__ __forceinline__ float sigf(float x) { return __fdividef(1.f, 1.f + __expf(-x)); }
__device__ __forceinline__ float tanha(float x) {
    float y; asm("tanh.approx.f32 %0, %1;" : "=f"(y) : "f"(x)); return y;
}
__device__ __forceinline__ float wsum(float v) {
#pragma unroll
    for (int o = 16; o > 0; o >>= 1) v += __shfl_xor_sync(0xffffffffu, v, o);
    return v;
}
__device__ __forceinline__ float wmax(float v) {
#pragma unroll
    for (int o = 16; o > 0; o >>= 1) v = fmaxf(v, __shfl_xor_sync(0xffffffffu, v, o));
    return v;
}

// ---------------- grid barrier ----------------
__device__ __forceinline__ void gbar() {
    __syncthreads();
    if (threadIdx.x == 0) {
        unsigned e = g_epoch;
        __threadfence();
        if (atomicAdd(&g_count, 1) == NB - 1) {
            g_count = 0;
            __threadfence();
            g_epoch = e + 1;
        } else {
            while (g_epoch == e) __nanosleep(64);
        }
        __threadfence();
    }
    __syncthreads();
}

// ---------------- shared memory ----------------
struct SLstm { float xs[2][64][B]; };
struct SAtt {
    float ahs[ARNN];
    float pqs[ATT]; float vs[ATT];
    float cat0[158]; float cat1[158];
    float cwsT[62][LOCF];
    float lls[ATT * LOCF];
    float lfs[128][LOCF + 1];
    float ep[256];
};
struct SSoft { float sw[TIN]; float red[8]; };
struct SProj { float sd[DRNN + ENC]; };
union Smem { SLstm l; SAtt a; SSoft s; SProj p; };

// ---------------- init ----------------
__global__ void zero_kernel() {
    int i = blockIdx.x * blockDim.x + threadIdx.x;
    if (i < ARNN * B) {
        g_ah[0][i] = 0.f; g_ah[1][i] = 0.f; g_ahbm[0][i] = 0.f; g_ahbm[1][i] = 0.f; g_ac[i] = 0.f;
        g_dh[0][i] = 0.f; g_dh[1][i] = 0.f; g_dhbm[0][i] = 0.f; g_dhbm[1][i] = 0.f; g_dc[i] = 0.f;
    }
    if (i < B * TIN) { g_aw[i] = 0.f; g_awc[i] = 0.f; }
    if (i < ENC * B) { g_actx[i] = 0.f; }
    if (i == 0) { g_count = 0; g_epoch = 0; }
}

// ---------------- prenet precompute -> g_pren[t][j][b] ----------------
__global__ __launch_bounds__(256)
void prenet_kernel(const float* __restrict__ dec, const float* __restrict__ w1,
                   const float* __restrict__ w2) {
    int t = blockIdx.x >> 5;
    int b = blockIdx.x & 31;
    int tid = threadIdx.x;
    __shared__ float xm[NMEL];
    __shared__ float x1[PRE];
    if (tid < NMEL)
        xm[tid] = (t == 0) ? 0.f : dec[(size_t)b * NMEL * TOUT + (size_t)tid * TOUT + (t - 1)];
    __syncthreads();
    {
        const float* w = w1 + tid * NMEL;
        float s = 0.f;
#pragma unroll
        for (int m = 0; m < NMEL; ++m) s += xm[m] * w[m];
        x1[tid] = fmaxf(s, 0.f);
    }
    __syncthreads();
    {
        const float* w = w2 + tid * PRE;
        float s = 0.f;
#pragma unroll 8
        for (int k = 0; k < PRE; ++k) s += x1[k] * w[k];
        g_pren[((size_t)t * PRE + tid) * B + b] = fmaxf(s, 0.f);
    }
}

// ---------------- pmemT precompute -> [b][a][t] ----------------
__global__ __launch_bounds__(128)
void pmem_kernel(const float* __restrict__ memory, const float* __restrict__ memw) {
    int b = blockIdx.x;
    int tb = blockIdx.y * 16;
    int a = threadIdx.x;
    __shared__ __align__(16) float xs[64][16];
    __shared__ float ws[128 * 65];
    float acc[16];
#pragma unroll
    for (int i = 0; i < 16; ++i) acc[i] = 0.f;
    for (int e0 = 0; e0 < ENC; e0 += 64) {
        __syncthreads();
#pragma unroll
        for (int i2 = 0; i2 < 8; ++i2) {
            int idx = a + i2 * 128;
            int ee = idx & 63, tt = idx >> 6;
            xs[ee][tt] = memory[(size_t)b * TIN * ENC + (size_t)(tb + tt) * ENC + e0 + ee];
        }
#pragma unroll
        for (int i2 = 0; i2 < 64; ++i2) {
            int idx = a + i2 * 128;
            int ee = idx & 63, aa = idx >> 6;
            ws[aa * 65 + ee] = memw[aa * ENC + e0 + ee];
        }
        __syncthreads();
#pragma unroll 4
        for (int ee = 0; ee < 64; ++ee) {
            float w = ws[a * 65 + ee];
            const float4* xr = (const float4*)&xs[ee][0];
            float4 v0 = xr[0], v1 = xr[1], v2 = xr[2], v3 = xr[3];
            acc[0] += w * v0.x; acc[1] += w * v0.y; acc[2] += w * v0.z; acc[3] += w * v0.w;
            acc[4] += w * v1.x; acc[5] += w * v1.y; acc[6] += w * v1.z; acc[7] += w * v1.w;
            acc[8] += w * v2.x; acc[9] += w * v2.y; acc[10] += w * v2.z; acc[11] += w * v2.w;
            acc[12] += w * v3.x; acc[13] += w * v3.y; acc[14] += w * v3.z; acc[15] += w * v3.w;
        }
    }
    float* o = g_pmemT + (size_t)b * ATT * TIN + (size_t)a * TIN + tb;
#pragma unroll
    for (int i = 0; i < 16; ++i) o[i] = acc[i];
}

// ---------------- LSTM GEMV split-K: 64 rowblocks x 4 kslices = 256 blocks --------
// thread: 2 rows x 4 batches (8 acc); writes partials to g_zpart[ks][j][b]
template <int WA, int WB>
__device__ void lstm_gemv(const float* __restrict__ srcA, const float* __restrict__ srcB,
                          const float* __restrict__ hprev,
                          const float* __restrict__ wih, const float* __restrict__ whh,
                          SLstm& s) {
    constexpr int KX = WA + WB;
    constexpr int KTOT = KX + 1024;
    constexpr int SLICE = KTOT / 4;
    constexpr int NCH = SLICE / 64;
    const int tid = threadIdx.x;
    const int rb = blockIdx.x & 63;         // row block (64 rows)
    const int ks = blockIdx.x >> 6;         // k slice
    const int bg = tid & 7;                 // batch group (4 batches)
    const int rg = tid >> 3;                // row group (2 rows)
    const int j0r = rb * 64 + rg * 2;
    const int kbase = ks * SLICE;
    float a0[4] = {0, 0, 0, 0}, a1[4] = {0, 0, 0, 0};
    // stage chunk 0
#pragma unroll
    for (int i = 0; i < 8; ++i) {
        int idx = tid + i * 256;
        int kk = idx >> 5, bb = idx & 31;
        int k = kbase + kk;
        float v;
        if (k < WA) v = srcA[k * B + bb];
        else if (k < KX) v = srcB[(k - WA) * B + bb];
        else v = hprev[(k - KX) * B + bb];
        s.xs[0][kk][bb] = v;
    }
    __syncthreads();
    for (int c = 0; c < NCH; ++c) {
        const int k0 = kbase + c * 64;
        const bool ih = (k0 < KX);
        const float* w0 = ih ? (wih + (size_t)j0r * KX + k0)
                             : (whh + (size_t)j0r * 1024 + (k0 - KX));
        const size_t wstr = ih ? KX : 1024;
        const float* w1 = w0 + wstr;
        float xr[8];
        if (c + 1 < NCH) {
            const int k0n = k0 + 64;
#pragma unroll
            for (int i = 0; i < 8; ++i) {
                int idx = tid + i * 256;
                int kk = idx >> 5, bb = idx & 31;
                int k = k0n + kk;
                float v;
                if (k < WA) v = srcA[k * B + bb];
                else if (k < KX) v = srcB[(k - WA) * B + bb];
                else v = hprev[(k - KX) * B + bb];
                xr[i] = v;
            }
        }
        const float (*xb)[B] = s.xs[c & 1];
#pragma unroll 4
        for (int q = 0; q < 16; ++q) {
            float4 wa = __ldg((const float4*)w0 + q);
            float4 wb = __ldg((const float4*)w1 + q);
            float4 x0 = *(const float4*)&xb[q * 4 + 0][bg * 4];
            float4 x1 = *(const float4*)&xb[q * 4 + 1][bg * 4];
            float4 x2 = *(const float4*)&xb[q * 4 + 2][bg * 4];
            float4 x3 = *(const float4*)&xb[q * 4 + 3][bg * 4];
            a0[0] += wa.x * x0.x; a0[1] += wa.x * x0.y; a0[2] += wa.x * x0.z; a0[3] += wa.x * x0.w;
            a1[0] += wb.x * x0.x; a1[1] += wb.x * x0.y; a1[2] += wb.x * x0.z; a1[3] += wb.x * x0.w;
            a0[0] += wa.y * x1.x; a0[1] += wa.y * x1.y; a0[2] += wa.y * x1.z; a0[3] += wa.y * x1.w;
            a1[0] += wb.y * x1.x; a1[1] += wb.y * x1.y; a1[2] += wb.y * x1.z; a1[3] += wb.y * x1.w;
            a0[0] += wa.z * x2.x; a0[1] += wa.z * x2.y; a0[2] += wa.z * x2.z; a0[3] += wa.z * x2.w;
            a1[0] += wb.z * x2.x; a1[1] += wb.z * x2.y; a1[2] += wb.z * x2.z; a1[3] += wb.z * x2.w;
            a0[0] += wa.w * x3.x; a0[1] += wa.w * x3.y; a0[2] += wa.w * x3.z; a0[3] += wa.w * x3.w;
            a1[0] += wb.w * x3.x; a1[1] += wb.w * x3.y; a1[2] += wb.w * x3.z; a1[3] += wb.w * x3.w;
        }
        if (c + 1 < NCH) {
#pragma unroll
            for (int i = 0; i < 8; ++i) {
                int idx = tid + i * 256;
                s.xs[(c + 1) & 1][idx >> 5][idx & 31] = xr[i];
            }
        }
        __syncthreads();
    }
    float* zp = g_zpart + ((size_t)ks * 4096 + j0r) * B + bg * 4;
    *(float4*)zp = make_float4(a0[0], a0[1], a0[2], a0[3]);
    *(float4*)(zp + B) = make_float4(a1[0], a1[1], a1[2], a1[3]);
}

// ---------------- LSTM gating: sum 4 partials + bias, nonlinearity, state update ----
template <int ISDEC>
__device__ void lstm_gate(const float* __restrict__ bih, const float* __restrict__ bhh,
                          int cur) {
    const int tid = threadIdx.x;
    if (tid >= 128) return;
    const int b = tid & 31;
    const int h = blockIdx.x * 4 + (tid >> 5);
    float z[4];
#pragma unroll
    for (int g = 0; g < 4; ++g) {
        const int j = g * 1024 + h;
        float sv = bih[j] + bhh[j];
#pragma unroll
        for (int ss = 0; ss < 4; ++ss)
            sv += g_zpart[((size_t)ss * 4096 + j) * B + b];
        z[g] = sv;
    }
    float* cst = ISDEC ? g_dc : g_ac;
    float* hout = ISDEC ? &g_dh[cur][0] : &g_ah[cur][0];
    float* hbm = ISDEC ? &g_dhbm[cur][0] : &g_ahbm[cur][0];
    float c = cst[h * B + b];
    float cn = sigf(z[1]) * c + sigf(z[0]) * tanhf(z[2]);
    cst[h * B + b] = cn;
    float hv = sigf(z[3]) * tanhf(cn);
    hout[h * B + b] = hv;
    hbm[b * 1024 + h] = hv;
}

// ---------------- energy phase: 128 blocks, 4 per batch, 128 t each ----------------
__device__ void energy_phase(const float* __restrict__ qw, const float* __restrict__ convw,
                             const float* __restrict__ loclin, const float* __restrict__ vw,
                             const int* __restrict__ lens, int cur, SAtt& s) {
    const int blk = blockIdx.x;
    const int b = blk >> 2;
    const int tbase = (blk & 3) * 128;
    const int tid = threadIdx.x, warp = tid >> 5, lane = tid & 31;
    ((float4*)s.ahs)[tid] = ((const float4*)&g_ahbm[cur][b * ARNN])[tid];
    for (int i = tid; i < 158; i += 256) {
        int tp = tbase - 15 + i;
        bool ok = (tp >= 0 && tp < TIN);
        s.cat0[i] = ok ? g_aw[b * TIN + tp] : 0.f;
        s.cat1[i] = ok ? g_awc[b * TIN + tp] : 0.f;
    }
    for (int i = tid; i < 62 * LOCF; i += 256) s.cwsT[i >> 5][i & 31] = convw[(i & 31) * 62 + (i >> 5)];
    for (int i = tid; i < ATT * LOCF; i += 256) s.lls[i] = loclin[i];
    if (tid < ATT) s.vs[tid] = vw[tid];
    __syncthreads();
    // pq: 8 warps x 16 rows (recomputed per block; tiny)
#pragma unroll 1
    for (int r = 0; r < 16; ++r) {
        int a = warp * 16 + r;
        const float4* w = (const float4*)(qw + (size_t)a * ARNN);
        const float4* hv = (const float4*)s.ahs;
        float acc = 0.f;
#pragma unroll
        for (int i = 0; i < 8; ++i) {
            float4 wv = __ldg(&w[lane + i * 32]);
            float4 xv = hv[lane + i * 32];
            acc += wv.x * xv.x + wv.y * xv.y + wv.z * xv.z + wv.w * xv.w;
        }
        acc = wsum(acc);
        if (lane == 0) s.pqs[a] = acc;
    }
    // conv: t = tid&127, half = tid>>7 computes 16 filters
    {
        const int t = tid & 127, hf = tid >> 7;
        float lf[16];
#pragma unroll
        for (int i = 0; i < 16; ++i) lf[i] = 0.f;
#pragma unroll 2
        for (int kc = 0; kc < 62; ++kc) {
            float cv = (kc < 31) ? s.cat0[t + kc] : s.cat1[t + kc - 31];
            const float4* w = (const float4*)&s.cwsT[kc][hf * 16];
            float4 w0 = w[0], w1 = w[1], w2 = w[2], w3 = w[3];
            lf[0] += cv * w0.x; lf[1] += cv * w0.y; lf[2] += cv * w0.z; lf[3] += cv * w0.w;
            lf[4] += cv * w1.x; lf[5] += cv * w1.y; lf[6] += cv * w1.z; lf[7] += cv * w1.w;
            lf[8] += cv * w2.x; lf[9] += cv * w2.y; lf[10] += cv * w2.z; lf[11] += cv * w2.w;
            lf[12] += cv * w3.x; lf[13] += cv * w3.y; lf[14] += cv * w3.z; lf[15] += cv * w3.w;
        }
#pragma unroll
        for (int i = 0; i < 16; ++i) s.lfs[t][hf * 16 + i] = lf[i];
    }
    __syncthreads();
    // energies: t = tid&127, a-half = tid>>7 (64 dims each)
    {
        const int t = tid & 127, ah = tid >> 7;
        float lfr[32];
#pragma unroll
        for (int i = 0; i < 32; ++i) lfr[i] = s.lfs[t][i];
        const float* pm = g_pmemT + (size_t)b * ATT * TIN + tbase + t;
        float e = 0.f;
#pragma unroll 2
        for (int a = ah * 64; a < ah * 64 + 64; ++a) {
            float s0 = s.pqs[a] + __ldg(&pm[(size_t)a * TIN]);
            const float4* ll = (const float4*)&s.lls[a * LOCF];
#pragma unroll
            for (int i = 0; i < 8; ++i) {
                float4 lv = ll[i];
                s0 += lv.x * lfr[i * 4] + lv.y * lfr[i * 4 + 1] + lv.z * lfr[i * 4 + 2] + lv.w * lfr[i * 4 + 3];
            }
            e += s.vs[a] * tanha(s0);
        }
        s.ep[tid] = e;
    }
    __syncthreads();
    if (tid < 128) {
        int tp = tbase + tid;
        float e = s.ep[tid] + s.ep[tid + 128];
        if (tp >= lens[b]) e = -1e9f;
        g_energy[b * TIN + tp] = e;
    }
}

// ---------------- softmax + context (blocks < 32) ----------------
__device__ void softctx_phase(const float* __restrict__ memory, int t,
                              float* __restrict__ out_align, SSoft& s) {
    const int b = blockIdx.x, tid = threadIdx.x;
    const int warp = tid >> 5, lane = tid & 31;
    float e0 = g_energy[b * TIN + tid];
    float e1 = g_energy[b * TIN + tid + 256];
    float m = fmaxf(e0, e1);
    m = wmax(m);
    if (lane == 0) s.red[warp] = m;
    __syncthreads();
    if (tid < 32) {
        float mm = (lane < 8) ? s.red[lane] : -3.4e38f;
        mm = wmax(mm);
        if (lane == 0) s.red[0] = mm;
    }
    __syncthreads();
    m = s.red[0];
    float p0 = __expf(e0 - m), p1 = __expf(e1 - m);
    float ps = wsum(p0 + p1);
    __syncthreads();
    if (lane == 0) s.red[warp] = ps;
    __syncthreads();
    if (tid < 32) {
        float ss = (lane < 8) ? s.red[lane] : 0.f;
        ss = wsum(ss);
        if (lane == 0) s.red[0] = ss;
    }
    __syncthreads();
    float inv = __fdividef(1.f, s.red[0]);
    float a0 = p0 * inv, a1 = p1 * inv;
    s.sw[tid] = a0; s.sw[tid + 256] = a1;
    g_aw[b * TIN + tid] = a0; g_aw[b * TIN + tid + 256] = a1;
    g_awc[b * TIN + tid] += a0; g_awc[b * TIN + tid + 256] += a1;
    float* oa = out_align + ((size_t)b * TOUT + t) * TIN;
    oa[tid] = a0; oa[tid + 256] = a1;
    __syncthreads();
    const float* mb = memory + (size_t)b * TIN * ENC + tid;
    float c0 = 0.f, c1 = 0.f;
#pragma unroll 4
    for (int tt = 0; tt < TIN; ++tt) {
        float w = s.sw[tt];
        c0 += w * __ldg(&mb[(size_t)tt * ENC]);
        c1 += w * __ldg(&mb[(size_t)tt * ENC + 256]);
    }
    g_actx[tid * B + b] = c0;
    g_actx[(tid + 256) * B + b] = c1;
    g_actxbm[b * ENC + tid] = c0;
    g_actxbm[b * ENC + tid + 256] = c1;
}

// ---------------- projection + gate (blocks < 32) ----------------
__device__ void proj_phase(const float* __restrict__ pw, const float* __restrict__ pb,
                           const float* __restrict__ gw, const float* __restrict__ gb,
                           int t, int cur, float* __restrict__ out_mel,
                           float* __restrict__ out_gate, SProj& s) {
    const int b = blockIdx.x, tid = threadIdx.x;
    const int warp = tid >> 5, lane = tid & 31;
    for (int i = tid; i < DRNN; i += 256) s.sd[i] = g_dhbm[cur][b * DRNN + i];
    for (int i = tid; i < ENC; i += 256) s.sd[DRNN + i] = g_actxbm[b * ENC + i];
    __syncthreads();
    for (int r = warp; r < NMEL + 1; r += 8) {
        const float4* w = (const float4*)((r < NMEL) ? (pw + (size_t)r * (DRNN + ENC)) : gw);
        const float4* x = (const float4*)s.sd;
        float acc = 0.f;
#pragma unroll
        for (int i = 0; i < 12; ++i) {
            float4 wv = __ldg(&w[lane + i * 32]);
            float4 xv = x[lane + i * 32];
            acc += wv.x * xv.x + wv.y * xv.y + wv.z * xv.z + wv.w * xv.w;
        }
        acc = wsum(acc);
        if (lane == 0) {
            if (r < NMEL) out_mel[(size_t)b * NMEL * TOUT + (size_t)r * TOUT + t] = acc + pb[r];
            else out_gate[(size_t)b * TOUT + t] = acc + gb[0];
        }
    }
    __syncthreads();
}

// ---------------- persistent decoder ----------------
__global__ __launch_bounds__(256, 2)
void persist_kernel(const float* __restrict__ memory,
                    const float* __restrict__ awih, const float* __restrict__ awhh,
                    const float* __restrict__ abih, const float* __restrict__ abhh,
                    const float* __restrict__ qw, const float* __restrict__ vw,
                    const float* __restrict__ convw, const float* __restrict__ loclin,
                    const float* __restrict__ dwih, const float* __restrict__ dwhh,
                    const float* __restrict__ dbih, const float* __restrict__ dbhh,
                    const float* __restrict__ pw, const float* __restrict__ pb,
                    const float* __restrict__ gw, const float* __restrict__ gb,
                    const int* __restrict__ lens,
                    float* __restrict__ out_mel, float* __restrict__ out_gate,
                    float* __restrict__ out_align) {
    extern __shared__ __align__(16) char smraw[];
    Smem& sm = *reinterpret_cast<Smem*>(smraw);
    for (int t = 0; t < TOUT; ++t) {
        const int cur = t & 1, prev = cur ^ 1;
        lstm_gemv<PRE, ENC>(g_pren + (size_t)t * PRE * B, g_actx, &g_ah[prev][0],
                            awih, awhh, sm.l);
        gbar();
        lstm_gate<0>(abih, abhh, cur);
        gbar();
        if (blockIdx.x < 128)
            energy_phase(qw, convw, loclin, vw, lens, cur, sm.a);
        gbar();
        if (blockIdx.x < 32)
            softctx_phase(memory, t, out_align, sm.s);
        gbar();
        lstm_gemv<ARNN, ENC>(&g_ah[cur][0], g_actx, &g_dh[prev][0],
                             dwih, dwhh, sm.l);
        gbar();
        lstm_gate<1>(dbih, dbhh, cur);
        gbar();
        if (blockIdx.x < 32)
            proj_phase(pw, pb, gw, gb, t, cur, out_mel, out_gate, sm.p);
        // proj(t) overlaps attn GEMV(t+1): disjoint buffers, ordered by barriers
    }
}

// ---------------- launch ----------------
extern "C" void kernel_launch(void* const* d_in, const int* in_sizes, int n_in,
                              void* d_out, int out_size) {
    const float* memory = (const float*)d_in[0];
    const float* dec    = (const float*)d_in[1];
    const float* w1     = (const float*)d_in[2];
    const float* w2     = (const float*)d_in[3];
    const float* awih   = (const float*)d_in[4];
    const float* awhh   = (const float*)d_in[5];
    const float* abih   = (const float*)d_in[6];
    const float* abhh   = (const float*)d_in[7];
    const float* qw     = (const float*)d_in[8];
    const float* memw   = (const float*)d_in[9];
    const float* vw     = (const float*)d_in[10];
    const float* convw  = (const float*)d_in[11];
    const float* loclin = (const float*)d_in[12];
    const float* dwih   = (const float*)d_in[13];
    const float* dwhh   = (const float*)d_in[14];
    const float* dbih   = (const float*)d_in[15];
    const float* dbhh   = (const float*)d_in[16];
    const float* pw     = (const float*)d_in[17];
    const float* pb     = (const float*)d_in[18];
    const float* gw     = (const float*)d_in[19];
    const float* gb     = (const float*)d_in[20];
    const int*   lens   = (const int*)d_in[21];

    float* out_mel = (float*)d_out;
    float* out_gate = out_mel + (size_t)B * NMEL * TOUT;
    float* out_align = out_gate + (size_t)B * TOUT;

    cudaFuncSetAttribute(persist_kernel, cudaFuncAttributeMaxDynamicSharedMemorySize,
                         (int)sizeof(Smem));

    zero_kernel<<<(ARNN * B + 255) / 256, 256>>>();
    prenet_kernel<<<TOUT * B, 256>>>(dec, w1, w2);
    pmem_kernel<<<dim3(B, TIN / 16), 128>>>(memory, memw);
    persist_kernel<<<NB, 256, sizeof(Smem)>>>(memory, awih, awhh, abih, abhh, qw, vw,
                                              convw, loclin, dwih, dwhh, dbih, dbhh,
                                              pw, pb, gw, gb, lens,
                                              out_mel, out_gate, out_align);
}

// round 7
// speedup vs baseline: 2.7239x; 1.3125x over previous
#include <cuda_runtime.h>
#include <math.h>

#define B 32
#define TIN 512
#define TOUT 800
#define NMEL 80
#define ENC 512
#define ARNN 1024
#define DRNN 1024
#define PRE 256
#define ATT 128
#define LOCF 32
#define LOCK 31
#define NB 128
#define NT 512

// ---------------- device state ----------------
static __device__ float g_pren[(size_t)TOUT * PRE * B];    // [t][j][b]
static __device__ float g_pmemT[(size_t)B * ATT * TIN];    // [b][a][t]
static __device__ float g_ah[2][ARNN * B];                 // [h][b]
static __device__ float g_ahbm[2][B * ARNN];               // [b][h]
static __device__ float g_ac[ARNN * B];
static __device__ float g_dh[2][DRNN * B];
static __device__ float g_dhbm[2][B * DRNN];
static __device__ float g_dc[DRNN * B];
static __device__ float g_aw[B * TIN];
static __device__ float g_awc[B * TIN];
static __device__ float g_ctxpart[2][4][ENC * B];          // [par][quarter][d][b]
static __device__ float g_energy[B * TIN];

// hierarchical barrier state (monotonic counters)
struct PadCnt { unsigned v; unsigned pad[31]; };
static __device__ PadCnt g_gcnt[8];
static __device__ __align__(128) unsigned g_root;
static __device__ __align__(128) volatile unsigned g_epoch;

__device__ __forceinline__ float sigf(float x) { return __fdividef(1.f, 1.f + __expf(-x)); }
__device__ __forceinline__ float tanha(float x) {
    float y; asm("tanh.approx.f32 %0, %1;" : "=f"(y) : "f"(x)); return y;
}
__device__ __forceinline__ float wsum(float v) {
#pragma unroll
    for (int o = 16; o > 0; o >>= 1) v += __shfl_xor_sync(0xffffffffu, v, o);
    return v;
}
__device__ __forceinline__ float wmax(float v) {
#pragma unroll
    for (int o = 16; o > 0; o >>= 1) v = fmaxf(v, __shfl_xor_sync(0xffffffffu, v, o));
    return v;
}

// ---------------- hierarchical grid barrier: 8 groups x 16 blocks ----------------
__device__ __forceinline__ void gbar() {
    __syncthreads();
    if (threadIdx.x == 0) {
        unsigned e = g_epoch;
        __threadfence();
        int grp = blockIdx.x >> 4;
        unsigned r = atomicAdd(&g_gcnt[grp].v, 1);
        if ((r & 15u) == 15u) {
            unsigned rr = atomicAdd(&g_root, 1);
            if ((rr & 7u) == 7u) {
                __threadfence();
                g_epoch = e + 1;
            }
        }
        while (g_epoch == e) __nanosleep(32);
        __threadfence();
    }
    __syncthreads();
}

// ---------------- shared memory ----------------
struct SLstm {
    float xs[2][4][64][B];       // [buf][kslice][kk][b]  64KB
    float zsp[4][32][B];         // [kslice][rowlocal][b] 16KB
};
struct SAtt {
    float ahs[ARNN];
    float pqs[ATT]; float vs[ATT];
    float cat0[158]; float cat1[158];
    float cwsT[62][LOCF];
    float lls[ATT * LOCF];
    float lfs[128][LOCF + 1];
    float ep[NT];
};
struct SSoft {
    float sw[TIN];
    float red[16];
    float sd[DRNN + ENC];
};
union Smem { SLstm l; SAtt a; SSoft s; };

// ---------------- init ----------------
__global__ void zero_kernel() {
    int i = blockIdx.x * blockDim.x + threadIdx.x;
    if (i < ARNN * B) {
        g_ah[0][i] = 0.f; g_ah[1][i] = 0.f; g_ahbm[0][i] = 0.f; g_ahbm[1][i] = 0.f; g_ac[i] = 0.f;
        g_dh[0][i] = 0.f; g_dh[1][i] = 0.f; g_dhbm[0][i] = 0.f; g_dhbm[1][i] = 0.f; g_dc[i] = 0.f;
    }
    if (i < B * TIN) { g_aw[i] = 0.f; g_awc[i] = 0.f; }
    if (i < 4 * ENC * B) { g_ctxpart[0][0][i] = 0.f; g_ctxpart[1][0][i] = 0.f; }
    if (i < 8) g_gcnt[i].v = 0;
    if (i == 0) { g_root = 0; g_epoch = 0; }
}

// ---------------- prenet precompute -> g_pren[t][j][b] ----------------
__global__ __launch_bounds__(256)
void prenet_kernel(const float* __restrict__ dec, const float* __restrict__ w1,
                   const float* __restrict__ w2) {
    int t = blockIdx.x >> 5;
    int b = blockIdx.x & 31;
    int tid = threadIdx.x;
    __shared__ float xm[NMEL];
    __shared__ float x1[PRE];
    if (tid < NMEL)
        xm[tid] = (t == 0) ? 0.f : dec[(size_t)b * NMEL * TOUT + (size_t)tid * TOUT + (t - 1)];
    __syncthreads();
    {
        const float* w = w1 + tid * NMEL;
        float s = 0.f;
#pragma unroll
        for (int m = 0; m < NMEL; ++m) s += xm[m] * w[m];
        x1[tid] = fmaxf(s, 0.f);
    }
    __syncthreads();
    {
        const float* w = w2 + tid * PRE;
        float s = 0.f;
#pragma unroll 8
        for (int k = 0; k < PRE; ++k) s += x1[k] * w[k];
        g_pren[((size_t)t * PRE + tid) * B + b] = fmaxf(s, 0.f);
    }
}

// ---------------- pmemT precompute -> [b][a][t] ----------------
__global__ __launch_bounds__(128)
void pmem_kernel(const float* __restrict__ memory, const float* __restrict__ memw) {
    int b = blockIdx.x;
    int tb = blockIdx.y * 16;
    int a = threadIdx.x;
    __shared__ __align__(16) float xs[64][16];
    __shared__ float ws[128 * 65];
    float acc[16];
#pragma unroll
    for (int i = 0; i < 16; ++i) acc[i] = 0.f;
    for (int e0 = 0; e0 < ENC; e0 += 64) {
        __syncthreads();
#pragma unroll
        for (int i2 = 0; i2 < 8; ++i2) {
            int idx = a + i2 * 128;
            int ee = idx & 63, tt = idx >> 6;
            xs[ee][tt] = memory[(size_t)b * TIN * ENC + (size_t)(tb + tt) * ENC + e0 + ee];
        }
#pragma unroll
        for (int i2 = 0; i2 < 64; ++i2) {
            int idx = a + i2 * 128;
            int ee = idx & 63, aa = idx >> 6;
            ws[aa * 65 + ee] = memw[aa * ENC + e0 + ee];
        }
        __syncthreads();
#pragma unroll 4
        for (int ee = 0; ee < 64; ++ee) {
            float w = ws[a * 65 + ee];
            const float4* xr = (const float4*)&xs[ee][0];
            float4 v0 = xr[0], v1 = xr[1], v2 = xr[2], v3 = xr[3];
            acc[0] += w * v0.x; acc[1] += w * v0.y; acc[2] += w * v0.z; acc[3] += w * v0.w;
            acc[4] += w * v1.x; acc[5] += w * v1.y; acc[6] += w * v1.z; acc[7] += w * v1.w;
            acc[8] += w * v2.x; acc[9] += w * v2.y; acc[10] += w * v2.z; acc[11] += w * v2.w;
            acc[12] += w * v3.x; acc[13] += w * v3.y; acc[14] += w * v3.z; acc[15] += w * v3.w;
        }
    }
    float* o = g_pmemT + (size_t)b * ATT * TIN + (size_t)a * TIN + tb;
#pragma unroll
    for (int i = 0; i < 16; ++i) o[i] = acc[i];
}

// ---------------- fused LSTM: in-block split-K=4 GEMV + gate ----------------
// srcB4 points at ctxpart[par][0]; the ENC segment is the sum of 4 quarter-partials.
template <int WA, int WB>
__device__ void lstm_fused(const float* __restrict__ srcA, const float* __restrict__ srcB4,
                           const float* __restrict__ hprev,
                           const float* __restrict__ wih, const float* __restrict__ whh,
                           const float* __restrict__ bih, const float* __restrict__ bhh,
                           float* __restrict__ cst, float* __restrict__ hout,
                           float* __restrict__ hbm, SLstm& s) {
    constexpr int KX = WA + WB;
    constexpr int KTOT = KX + 1024;
    constexpr int SLICE = KTOT / 4;
    constexpr int NR = SLICE / 64;
    const int tid = threadIdx.x;
    const int ks = tid >> 7;          // K slice 0..3
    const int sub = tid & 127;
    const int rg = sub >> 3;          // rowgroup 0..15
    const int bg = sub & 7;           // batchgroup (4 batches)
    const int g = rg >> 2, p = rg & 3;
    const int h0 = blockIdx.x * 8;
    const int j0 = g * 1024 + h0 + p * 2;   // rows j0, j0+1
    const int kbase = ks * SLICE;
    const float* wihr = wih + (size_t)j0 * KX;
    const float* whhr = whh + (size_t)j0 * 1024;
    float a0[4] = {0, 0, 0, 0}, a1[4] = {0, 0, 0, 0};

    // stage round 0: 4 slices x 64 k x 32 b = 8192 floats, 16 per thread
#pragma unroll
    for (int i = 0; i < 16; ++i) {
        int idx = tid + i * NT;
        int ksl = idx >> 11, kk = (idx >> 5) & 63, bb = idx & 31;
        int k = ksl * SLICE + kk;
        float v;
        if (k < WA) v = srcA[k * B + bb];
        else if (k < KX) {
            const float* pp = srcB4 + (k - WA) * B + bb;
            v = pp[0] + pp[ENC * B] + pp[2 * ENC * B] + pp[3 * ENC * B];
        } else v = hprev[(k - KX) * B + bb];
        s.xs[0][ksl][kk][bb] = v;
    }
    __syncthreads();
    for (int c = 0; c < NR; ++c) {
        const int k0 = kbase + c * 64;
        const bool ih = (k0 < KX);
        const float* w0 = ih ? (wihr + k0) : (whhr + (k0 - KX));
        const float* w1 = w0 + (ih ? KX : 1024);
        float xr[16];
        if (c + 1 < NR) {
#pragma unroll
            for (int i = 0; i < 16; ++i) {
                int idx = tid + i * NT;
                int ksl = idx >> 11, kk = (idx >> 5) & 63, bb = idx & 31;
                int k = ksl * SLICE + (c + 1) * 64 + kk;
                float v;
                if (k < WA) v = srcA[k * B + bb];
                else if (k < KX) {
                    const float* pp = srcB4 + (k - WA) * B + bb;
                    v = pp[0] + pp[ENC * B] + pp[2 * ENC * B] + pp[3 * ENC * B];
                } else v = hprev[(k - KX) * B + bb];
                xr[i] = v;
            }
        }
        const float (*xb)[B] = s.xs[c & 1][ks];
#pragma unroll 4
        for (int q = 0; q < 16; ++q) {
            float4 wa = __ldg((const float4*)w0 + q);
            float4 wb = __ldg((const float4*)w1 + q);
            float4 x0 = *(const float4*)&xb[q * 4 + 0][bg * 4];
            float4 x1 = *(const float4*)&xb[q * 4 + 1][bg * 4];
            float4 x2 = *(const float4*)&xb[q * 4 + 2][bg * 4];
            float4 x3 = *(const float4*)&xb[q * 4 + 3][bg * 4];
            a0[0] += wa.x * x0.x; a0[1] += wa.x * x0.y; a0[2] += wa.x * x0.z; a0[3] += wa.x * x0.w;
            a1[0] += wb.x * x0.x; a1[1] += wb.x * x0.y; a1[2] += wb.x * x0.z; a1[3] += wb.x * x0.w;
            a0[0] += wa.y * x1.x; a0[1] += wa.y * x1.y; a0[2] += wa.y * x1.z; a0[3] += wa.y * x1.w;
            a1[0] += wb.y * x1.x; a1[1] += wb.y * x1.y; a1[2] += wb.y * x1.z; a1[3] += wb.y * x1.w;
            a0[0] += wa.z * x2.x; a0[1] += wa.z * x2.y; a0[2] += wa.z * x2.z; a0[3] += wa.z * x2.w;
            a1[0] += wb.z * x2.x; a1[1] += wb.z * x2.y; a1[2] += wb.z * x2.z; a1[3] += wb.z * x2.w;
            a0[0] += wa.w * x3.x; a0[1] += wa.w * x3.y; a0[2] += wa.w * x3.z; a0[3] += wa.w * x3.w;
            a1[0] += wb.w * x3.x; a1[1] += wb.w * x3.y; a1[2] += wb.w * x3.z; a1[3] += wb.w * x3.w;
        }
        if (c + 1 < NR) {
#pragma unroll
            for (int i = 0; i < 16; ++i) {
                int idx = tid + i * NT;
                s.xs[(c + 1) & 1][idx >> 11][(idx >> 5) & 63][idx & 31] = xr[i];
            }
        }
        __syncthreads();
    }
    // write partials: rowlocal = g*8 + p*2 + rr
    {
        const int rl0 = g * 8 + p * 2;
        float* z0 = &s.zsp[ks][rl0][bg * 4];
        float* z1 = &s.zsp[ks][rl0 + 1][bg * 4];
        *(float4*)z0 = make_float4(a0[0], a0[1], a0[2], a0[3]);
        *(float4*)z1 = make_float4(a1[0], a1[1], a1[2], a1[3]);
    }
    __syncthreads();
    // gate: 256 threads, thread = (hl, b)
    if (tid < 256) {
        const int hl = tid >> 5, b = tid & 31;
        const int h = h0 + hl;
        float z[4];
#pragma unroll
        for (int gg = 0; gg < 4; ++gg) {
            const int j = gg * 1024 + h;
            float sv = bih[j] + bhh[j];
#pragma unroll
            for (int q = 0; q < 4; ++q) sv += s.zsp[q][gg * 8 + hl][b];
            z[gg] = sv;
        }
        float c = cst[h * B + b];
        float cn = sigf(z[1]) * c + sigf(z[0]) * tanhf(z[2]);
        cst[h * B + b] = cn;
        float hv = sigf(z[3]) * tanhf(cn);
        hout[h * B + b] = hv;
        hbm[b * 1024 + h] = hv;
    }
}

// ---------------- energy phase: 128 blocks = (b, quarter), 128 t each ----------------
__device__ void energy_phase(const float* __restrict__ qw, const float* __restrict__ convw,
                             const float* __restrict__ loclin, const float* __restrict__ vw,
                             const int* __restrict__ lens, int cur, SAtt& s) {
    const int b = blockIdx.x >> 2;
    const int tbase = (blockIdx.x & 3) * 128;
    const int tid = threadIdx.x, warp = tid >> 5, lane = tid & 31;
    if (tid < 256) ((float4*)s.ahs)[tid] = ((const float4*)&g_ahbm[cur][b * ARNN])[tid];
    for (int i = tid; i < 158; i += NT) {
        int tp = tbase - 15 + i;
        bool ok = (tp >= 0 && tp < TIN);
        s.cat0[i] = ok ? g_aw[b * TIN + tp] : 0.f;
        s.cat1[i] = ok ? g_awc[b * TIN + tp] : 0.f;
    }
    for (int i = tid; i < 62 * LOCF; i += NT) s.cwsT[i >> 5][i & 31] = convw[(i & 31) * 62 + (i >> 5)];
    for (int i = tid; i < ATT * LOCF; i += NT) s.lls[i] = loclin[i];
    if (tid < ATT) s.vs[tid] = vw[tid];
    __syncthreads();
    // pq: 16 warps x 8 rows
#pragma unroll 1
    for (int r = 0; r < 8; ++r) {
        int a = warp * 8 + r;
        const float4* w = (const float4*)(qw + (size_t)a * ARNN);
        const float4* hv = (const float4*)s.ahs;
        float acc = 0.f;
#pragma unroll
        for (int i = 0; i < 8; ++i) {
            float4 wv = __ldg(&w[lane + i * 32]);
            float4 xv = hv[lane + i * 32];
            acc += wv.x * xv.x + wv.y * xv.y + wv.z * xv.z + wv.w * xv.w;
        }
        acc = wsum(acc);
        if (lane == 0) s.pqs[a] = acc;
    }
    // conv: thread (t = tid&127, fq = tid>>7) computes 8 filters
    {
        const int t = tid & 127, fq = tid >> 7;
        float lf[8];
#pragma unroll
        for (int i = 0; i < 8; ++i) lf[i] = 0.f;
#pragma unroll 2
        for (int kc = 0; kc < 62; ++kc) {
            float cv = (kc < 31) ? s.cat0[t + kc] : s.cat1[t + kc - 31];
            const float4* w = (const float4*)&s.cwsT[kc][fq * 8];
            float4 w0 = w[0], w1 = w[1];
            lf[0] += cv * w0.x; lf[1] += cv * w0.y; lf[2] += cv * w0.z; lf[3] += cv * w0.w;
            lf[4] += cv * w1.x; lf[5] += cv * w1.y; lf[6] += cv * w1.z; lf[7] += cv * w1.w;
        }
#pragma unroll
        for (int i = 0; i < 8; ++i) s.lfs[t][fq * 8 + i] = lf[i];
    }
    __syncthreads();
    // energies: thread (t, aq = tid>>7) handles 32 attention dims
    {
        const int t = tid & 127, aq = tid >> 7;
        float lfr[32];
#pragma unroll
        for (int i = 0; i < 32; ++i) lfr[i] = s.lfs[t][i];
        const float* pm = g_pmemT + (size_t)b * ATT * TIN + tbase + t;
        float e = 0.f;
#pragma unroll 2
        for (int a = aq * 32; a < aq * 32 + 32; ++a) {
            float s0 = s.pqs[a] + __ldg(&pm[(size_t)a * TIN]);
            const float4* ll = (const float4*)&s.lls[a * LOCF];
#pragma unroll
            for (int i = 0; i < 8; ++i) {
                float4 lv = ll[i];
                s0 += lv.x * lfr[i * 4] + lv.y * lfr[i * 4 + 1] + lv.z * lfr[i * 4 + 2] + lv.w * lfr[i * 4 + 3];
            }
            e += s.vs[a] * tanha(s0);
        }
        s.ep[tid] = e;
    }
    __syncthreads();
    if (tid < 128) {
        int tp = tbase + tid;
        float e = s.ep[tid] + s.ep[tid + 128] + s.ep[tid + 256] + s.ep[tid + 384];
        if (tp >= lens[b]) e = -1e9f;
        g_energy[b * TIN + tp] = e;
    }
}

// ---------------- softmax + partial context; q==3 blocks then do proj(t-1) ----------
__device__ void softctx_phase(const float* __restrict__ memory, int t, int cur,
                              float* __restrict__ out_align, SSoft& s) {
    const int b = blockIdx.x >> 2;
    const int q = blockIdx.x & 3;
    const int t0 = q * 128;
    const int tid = threadIdx.x, warp = tid >> 5, lane = tid & 31;
    float e = g_energy[b * TIN + tid];
    float m = wmax(e);
    if (lane == 0) s.red[warp] = m;
    __syncthreads();
    if (tid < 32) {
        float mm = (lane < 16) ? s.red[lane] : -3.4e38f;
        mm = wmax(mm);
        if (lane == 0) s.red[0] = mm;
    }
    __syncthreads();
    m = s.red[0];
    float p = __expf(e - m);
    float ps = wsum(p);
    __syncthreads();
    if (lane == 0) s.red[warp] = ps;
    __syncthreads();
    if (tid < 32) {
        float ss = (lane < 16) ? s.red[lane] : 0.f;
        ss = wsum(ss);
        if (lane == 0) s.red[0] = ss;
    }
    __syncthreads();
    float inv = __fdividef(1.f, s.red[0]);
    float aw = p * inv;
    s.sw[tid] = aw;
    if (tid >= t0 && tid < t0 + 128) {
        g_aw[b * TIN + tid] = aw;
        g_awc[b * TIN + tid] += aw;
        out_align[((size_t)b * TOUT + t) * TIN + tid] = aw;
    }
    __syncthreads();
    // partial context: this block covers t in [t0, t0+128), all 512 d (1 per thread)
    {
        const float* mb = memory + (size_t)b * TIN * ENC + (size_t)t0 * ENC + tid;
        float acc = 0.f;
#pragma unroll 4
        for (int tt = 0; tt < 128; ++tt)
            acc += s.sw[t0 + tt] * __ldg(&mb[(size_t)tt * ENC]);
        g_ctxpart[cur][q][tid * B + b] = acc;
    }
}

// ---------------- projection + gate for step tp (par = tp&1) ----------------
__device__ void proj_phase(const float* __restrict__ pw, const float* __restrict__ pb,
                           const float* __restrict__ gw, const float* __restrict__ gb,
                           int tp, int b, float* __restrict__ out_mel,
                           float* __restrict__ out_gate, SSoft& s) {
    const int par = tp & 1;
    const int tid = threadIdx.x, warp = tid >> 5, lane = tid & 31;
    __syncthreads();
    for (int i = tid; i < DRNN; i += NT) s.sd[i] = g_dhbm[par][b * DRNN + i];
    for (int i = tid; i < ENC; i += NT) {
        const float* pp = &g_ctxpart[par][0][i * B + b];
        s.sd[DRNN + i] = pp[0] + pp[ENC * B] + pp[2 * ENC * B] + pp[3 * ENC * B];
    }
    __syncthreads();
    for (int r = warp; r < NMEL + 1; r += 16) {
        const float4* w = (const float4*)((r < NMEL) ? (pw + (size_t)r * (DRNN + ENC)) : gw);
        const float4* x = (const float4*)s.sd;
        float acc = 0.f;
#pragma unroll
        for (int i = 0; i < 12; ++i) {
            float4 wv = __ldg(&w[lane + i * 32]);
            float4 xv = x[lane + i * 32];
            acc += wv.x * xv.x + wv.y * xv.y + wv.z * xv.z + wv.w * xv.w;
        }
        acc = wsum(acc);
        if (lane == 0) {
            if (r < NMEL) out_mel[(size_t)b * NMEL * TOUT + (size_t)r * TOUT + tp] = acc + pb[r];
            else out_gate[(size_t)b * TOUT + tp] = acc + gb[0];
        }
    }
}

// ---------------- persistent decoder ----------------
__global__ __launch_bounds__(NT, 1)
void persist_kernel(const float* __restrict__ memory,
                    const float* __restrict__ awih, const float* __restrict__ awhh,
                    const float* __restrict__ abih, const float* __restrict__ abhh,
                    const float* __restrict__ qw, const float* __restrict__ vw,
                    const float* __restrict__ convw, const float* __restrict__ loclin,
                    const float* __restrict__ dwih, const float* __restrict__ dwhh,
                    const float* __restrict__ dbih, const float* __restrict__ dbhh,
                    const float* __restrict__ pw, const float* __restrict__ pb,
                    const float* __restrict__ gw, const float* __restrict__ gb,
                    const int* __restrict__ lens,
                    float* __restrict__ out_mel, float* __restrict__ out_gate,
                    float* __restrict__ out_align) {
    extern __shared__ __align__(16) char smraw[];
    Smem& sm = *reinterpret_cast<Smem*>(smraw);
    for (int t = 0; t < TOUT; ++t) {
        const int cur = t & 1, prev = cur ^ 1;
        // phase 1: attention LSTM (srcB = actx(t-1) = ctxpart[prev])
        lstm_fused<PRE, ENC>(g_pren + (size_t)t * PRE * B, g_ctxpart[prev][0], &g_ah[prev][0],
                             awih, awhh, abih, abhh, g_ac, &g_ah[cur][0], &g_ahbm[cur][0], sm.l);
        gbar();
        // phase 2: attention energies
        energy_phase(qw, convw, loclin, vw, lens, cur, sm.a);
        gbar();
        // phase 3: softmax + partial context; q==3 blocks also run proj(t-1)
        softctx_phase(memory, t, cur, out_align, sm.s);
        if ((blockIdx.x & 3) == 3 && t > 0)
            proj_phase(pw, pb, gw, gb, t - 1, blockIdx.x >> 2, out_mel, out_gate, sm.s);
        gbar();
        // phase 4: decoder LSTM (srcA = ah(t), srcB = actx(t) = ctxpart[cur])
        lstm_fused<ARNN, ENC>(&g_ah[cur][0], g_ctxpart[cur][0], &g_dh[prev][0],
                              dwih, dwhh, dbih, dbhh, g_dc, &g_dh[cur][0], &g_dhbm[cur][0], sm.l);
        gbar();
    }
    // final projection for t = TOUT-1
    if (blockIdx.x < 32)
        proj_phase(pw, pb, gw, gb, TOUT - 1, blockIdx.x, out_mel, out_gate, sm.s);
}

// ---------------- launch ----------------
extern "C" void kernel_launch(void* const* d_in, const int* in_sizes, int n_in,
                              void* d_out, int out_size) {
    const float* memory = (const float*)d_in[0];
    const float* dec    = (const float*)d_in[1];
    const float* w1     = (const float*)d_in[2];
    const float* w2     = (const float*)d_in[3];
    const float* awih   = (const float*)d_in[4];
    const float* awhh   = (const float*)d_in[5];
    const float* abih   = (const float*)d_in[6];
    const float* abhh   = (const float*)d_in[7];
    const float* qw     = (const float*)d_in[8];
    const float* memw   = (const float*)d_in[9];
    const float* vw     = (const float*)d_in[10];
    const float* convw  = (const float*)d_in[11];
    const float* loclin = (const float*)d_in[12];
    const float* dwih   = (const float*)d_in[13];
    const float* dwhh   = (const float*)d_in[14];
    const float* dbih   = (const float*)d_in[15];
    const float* dbhh   = (const float*)d_in[16];
    const float* pw     = (const float*)d_in[17];
    const float* pb     = (const float*)d_in[18];
    const float* gw     = (const float*)d_in[19];
    const float* gb     = (const float*)d_in[20];
    const int*   lens   = (const int*)d_in[21];

    float* out_mel = (float*)d_out;
    float* out_gate = out_mel + (size_t)B * NMEL * TOUT;
    float* out_align = out_gate + (size_t)B * TOUT;

    cudaFuncSetAttribute(persist_kernel, cudaFuncAttributeMaxDynamicSharedMemorySize,
                         (int)sizeof(Smem));

    zero_kernel<<<(4 * ENC * B + 255) / 256, 256>>>();
    prenet_kernel<<<TOUT * B, 256>>>(dec, w1, w2);
    pmem_kernel<<<dim3(B, TIN / 16), 128>>>(memory, memw);
    persist_kernel<<<NB, NT, sizeof(Smem)>>>(memory, awih, awhh, abih, abhh, qw, vw,
                                             convw, loclin, dwih, dwhh, dbih, dbhh,
                                             pw, pb, gw, gb, lens,
                                             out_mel, out_gate, out_align);
}

// round 8
// speedup vs baseline: 2.7324x; 1.0031x over previous
#include <cuda_runtime.h>
#include <math.h>

#define B 32
#define TIN 512
#define TOUT 800
#define NMEL 80
#define ENC 512
#define ARNN 1024
#define DRNN 1024
#define PRE 256
#define ATT 128
#define LOCF 32
#define LOCK 31
#define NB 128
#define NT 512

// ---------------- device state ----------------
static __device__ float g_pren[(size_t)TOUT * PRE * B];    // [t][j][b]
static __device__ float g_pmemT[(size_t)B * ATT * TIN];    // [b][a][t]
static __device__ float g_ah[2][ARNN * B];                 // [h][b]
static __device__ float g_ahbm[2][B * ARNN];               // [b][h]
static __device__ float g_ac[ARNN * B];
static __device__ float g_dh[2][DRNN * B];
static __device__ float g_dhbm[2][B * DRNN];
static __device__ float g_dc[DRNN * B];
static __device__ float g_aw[B * TIN];
static __device__ float g_awc[B * TIN];
static __device__ float g_ctxpart[2][4][ENC * B];          // [par][quarter][d][b]
static __device__ float g_energy[B * TIN];

// hierarchical barrier state (monotonic counters)
struct PadCnt { unsigned v; unsigned pad[31]; };
static __device__ PadCnt g_gcnt[8];
static __device__ __align__(128) unsigned g_root;
static __device__ __align__(128) volatile unsigned g_epoch;

__device__ __forceinline__ float sigf(float x) { return __fdividef(1.f, 1.f + __expf(-x)); }
__device__ __forceinline__ float tanha(float x) {
    float y; asm("tanh.approx.f32 %0, %1;" : "=f"(y) : "f"(x)); return y;
}
__device__ __forceinline__ float wsum(float v) {
#pragma unroll
    for (int o = 16; o > 0; o >>= 1) v += __shfl_xor_sync(0xffffffffu, v, o);
    return v;
}
__device__ __forceinline__ float wmax(float v) {
#pragma unroll
    for (int o = 16; o > 0; o >>= 1) v = fmaxf(v, __shfl_xor_sync(0xffffffffu, v, o));
    return v;
}

// ---------------- hierarchical grid barrier: 8 groups x 16 blocks ----------------
__device__ __forceinline__ void gbar() {
    __syncthreads();
    if (threadIdx.x == 0) {
        unsigned e = g_epoch;
        __threadfence();
        int grp = blockIdx.x >> 4;
        unsigned r = atomicAdd(&g_gcnt[grp].v, 1);
        if ((r & 15u) == 15u) {
            unsigned rr = atomicAdd(&g_root, 1);
            if ((rr & 7u) == 7u) {
                __threadfence();
                g_epoch = e + 1;
            }
        }
        while (g_epoch == e) __nanosleep(32);
        __threadfence();
    }
    __syncthreads();
}

// ---------------- shared memory ----------------
struct SLstm {
    float xs[2][4][64][B];       // [buf][kslice][kk][b]  64KB
    float zsp[4][32][B];         // [kslice][rowlocal][b] 16KB
};
struct SAtt {
    float ahs[ARNN];
    float pqs[ATT]; float vs[ATT];
    float cat0[158]; float cat1[158];
    float cwsT[62][LOCF];
    float lls[ATT * LOCF];
    float lfs[128][LOCF + 1];
    float ep[NT];
};
struct SSoft {
    float sw[TIN];
    float red[16];
    float sd[DRNN + ENC];
};
union Smem { SLstm l; SAtt a; SSoft s; };

// ---------------- init ----------------
__global__ void zero_kernel() {
    int i = blockIdx.x * blockDim.x + threadIdx.x;
    if (i < ARNN * B) {
        g_ah[0][i] = 0.f; g_ah[1][i] = 0.f; g_ahbm[0][i] = 0.f; g_ahbm[1][i] = 0.f; g_ac[i] = 0.f;
        g_dh[0][i] = 0.f; g_dh[1][i] = 0.f; g_dhbm[0][i] = 0.f; g_dhbm[1][i] = 0.f; g_dc[i] = 0.f;
    }
    if (i < B * TIN) { g_aw[i] = 0.f; g_awc[i] = 0.f; }
    if (i < 4 * ENC * B) { g_ctxpart[0][0][i] = 0.f; g_ctxpart[1][0][i] = 0.f; }
    if (i < 8) g_gcnt[i].v = 0;
    if (i == 0) { g_root = 0; g_epoch = 0; }
}

// ---------------- prenet precompute -> g_pren[t][j][b] ----------------
__global__ __launch_bounds__(256)
void prenet_kernel(const float* __restrict__ dec, const float* __restrict__ w1,
                   const float* __restrict__ w2) {
    int t = blockIdx.x >> 5;
    int b = blockIdx.x & 31;
    int tid = threadIdx.x;
    __shared__ float xm[NMEL];
    __shared__ float x1[PRE];
    if (tid < NMEL)
        xm[tid] = (t == 0) ? 0.f : dec[(size_t)b * NMEL * TOUT + (size_t)tid * TOUT + (t - 1)];
    __syncthreads();
    {
        const float* w = w1 + tid * NMEL;
        float s = 0.f;
#pragma unroll
        for (int m = 0; m < NMEL; ++m) s += xm[m] * w[m];
        x1[tid] = fmaxf(s, 0.f);
    }
    __syncthreads();
    {
        const float* w = w2 + tid * PRE;
        float s = 0.f;
#pragma unroll 8
        for (int k = 0; k < PRE; ++k) s += x1[k] * w[k];
        g_pren[((size_t)t * PRE + tid) * B + b] = fmaxf(s, 0.f);
    }
}

// ---------------- pmemT precompute -> [b][a][t] ----------------
__global__ __launch_bounds__(128)
void pmem_kernel(const float* __restrict__ memory, const float* __restrict__ memw) {
    int b = blockIdx.x;
    int tb = blockIdx.y * 16;
    int a = threadIdx.x;
    __shared__ __align__(16) float xs[64][16];
    __shared__ float ws[128 * 65];
    float acc[16];
#pragma unroll
    for (int i = 0; i < 16; ++i) acc[i] = 0.f;
    for (int e0 = 0; e0 < ENC; e0 += 64) {
        __syncthreads();
#pragma unroll
        for (int i2 = 0; i2 < 8; ++i2) {
            int idx = a + i2 * 128;
            int ee = idx & 63, tt = idx >> 6;
            xs[ee][tt] = memory[(size_t)b * TIN * ENC + (size_t)(tb + tt) * ENC + e0 + ee];
        }
#pragma unroll
        for (int i2 = 0; i2 < 64; ++i2) {
            int idx = a + i2 * 128;
            int ee = idx & 63, aa = idx >> 6;
            ws[aa * 65 + ee] = memw[aa * ENC + e0 + ee];
        }
        __syncthreads();
#pragma unroll 4
        for (int ee = 0; ee < 64; ++ee) {
            float w = ws[a * 65 + ee];
            const float4* xr = (const float4*)&xs[ee][0];
            float4 v0 = xr[0], v1 = xr[1], v2 = xr[2], v3 = xr[3];
            acc[0] += w * v0.x; acc[1] += w * v0.y; acc[2] += w * v0.z; acc[3] += w * v0.w;
            acc[4] += w * v1.x; acc[5] += w * v1.y; acc[6] += w * v1.z; acc[7] += w * v1.w;
            acc[8] += w * v2.x; acc[9] += w * v2.y; acc[10] += w * v2.z; acc[11] += w * v2.w;
            acc[12] += w * v3.x; acc[13] += w * v3.y; acc[14] += w * v3.z; acc[15] += w * v3.w;
        }
    }
    float* o = g_pmemT + (size_t)b * ATT * TIN + (size_t)a * TIN + tb;
#pragma unroll
    for (int i = 0; i < 16; ++i) o[i] = acc[i];
}

// ---------------- fused LSTM: in-block split-K=4 GEMV + gate ----------------
// srcB4 points at ctxpart[par][0]; the ENC segment is the sum of 4 quarter-partials.
template <int WA, int WB>
__device__ void lstm_fused(const float* __restrict__ srcA, const float* __restrict__ srcB4,
                           const float* __restrict__ hprev,
                           const float* __restrict__ wih, const float* __restrict__ whh,
                           const float* __restrict__ bih, const float* __restrict__ bhh,
                           float* __restrict__ cst, float* __restrict__ hout,
                           float* __restrict__ hbm, SLstm& s) {
    constexpr int KX = WA + WB;
    constexpr int KTOT = KX + 1024;
    constexpr int SLICE = KTOT / 4;
    constexpr int NR = SLICE / 64;
    const int tid = threadIdx.x;
    const int ks = tid >> 7;          // K slice 0..3
    const int sub = tid & 127;
    const int rg = sub >> 3;          // rowgroup 0..15
    const int bg = sub & 7;           // batchgroup (4 batches)
    const int g = rg >> 2, p = rg & 3;
    const int h0 = blockIdx.x * 8;
    const int j0 = g * 1024 + h0 + p * 2;   // rows j0, j0+1
    const int kbase = ks * SLICE;
    const float* wihr = wih + (size_t)j0 * KX;
    const float* whhr = whh + (size_t)j0 * 1024;
    float a0[4] = {0, 0, 0, 0}, a1[4] = {0, 0, 0, 0};

    // stage round 0: 4 slices x 64 k x 32 b = 8192 floats, 16 per thread
#pragma unroll
    for (int i = 0; i < 16; ++i) {
        int idx = tid + i * NT;
        int ksl = idx >> 11, kk = (idx >> 5) & 63, bb = idx & 31;
        int k = ksl * SLICE + kk;
        float v;
        if (k < WA) v = srcA[k * B + bb];
        else if (k < KX) {
            const float* pp = srcB4 + (k - WA) * B + bb;
            v = pp[0] + pp[ENC * B] + pp[2 * ENC * B] + pp[3 * ENC * B];
        } else v = hprev[(k - KX) * B + bb];
        s.xs[0][ksl][kk][bb] = v;
    }
    __syncthreads();
    for (int c = 0; c < NR; ++c) {
        const int k0 = kbase + c * 64;
        const bool ih = (k0 < KX);
        const float* w0 = ih ? (wihr + k0) : (whhr + (k0 - KX));
        const float* w1 = w0 + (ih ? KX : 1024);
        float xr[16];
        if (c + 1 < NR) {
#pragma unroll
            for (int i = 0; i < 16; ++i) {
                int idx = tid + i * NT;
                int ksl = idx >> 11, kk = (idx >> 5) & 63, bb = idx & 31;
                int k = ksl * SLICE + (c + 1) * 64 + kk;
                float v;
                if (k < WA) v = srcA[k * B + bb];
                else if (k < KX) {
                    const float* pp = srcB4 + (k - WA) * B + bb;
                    v = pp[0] + pp[ENC * B] + pp[2 * ENC * B] + pp[3 * ENC * B];
                } else v = hprev[(k - KX) * B + bb];
                xr[i] = v;
            }
        }
        const float (*xb)[B] = s.xs[c & 1][ks];
#pragma unroll 4
        for (int q = 0; q < 16; ++q) {
            float4 wa = __ldg((const float4*)w0 + q);
            float4 wb = __ldg((const float4*)w1 + q);
            float4 x0 = *(const float4*)&xb[q * 4 + 0][bg * 4];
            float4 x1 = *(const float4*)&xb[q * 4 + 1][bg * 4];
            float4 x2 = *(const float4*)&xb[q * 4 + 2][bg * 4];
            float4 x3 = *(const float4*)&xb[q * 4 + 3][bg * 4];
            a0[0] += wa.x * x0.x; a0[1] += wa.x * x0.y; a0[2] += wa.x * x0.z; a0[3] += wa.x * x0.w;
            a1[0] += wb.x * x0.x; a1[1] += wb.x * x0.y; a1[2] += wb.x * x0.z; a1[3] += wb.x * x0.w;
            a0[0] += wa.y * x1.x; a0[1] += wa.y * x1.y; a0[2] += wa.y * x1.z; a0[3] += wa.y * x1.w;
            a1[0] += wb.y * x1.x; a1[1] += wb.y * x1.y; a1[2] += wb.y * x1.z; a1[3] += wb.y * x1.w;
            a0[0] += wa.z * x2.x; a0[1] += wa.z * x2.y; a0[2] += wa.z * x2.z; a0[3] += wa.z * x2.w;
            a1[0] += wb.z * x2.x; a1[1] += wb.z * x2.y; a1[2] += wb.z * x2.z; a1[3] += wb.z * x2.w;
            a0[0] += wa.w * x3.x; a0[1] += wa.w * x3.y; a0[2] += wa.w * x3.z; a0[3] += wa.w * x3.w;
            a1[0] += wb.w * x3.x; a1[1] += wb.w * x3.y; a1[2] += wb.w * x3.z; a1[3] += wb.w * x3.w;
        }
        if (c + 1 < NR) {
#pragma unroll
            for (int i = 0; i < 16; ++i) {
                int idx = tid + i * NT;
                s.xs[(c + 1) & 1][idx >> 11][(idx >> 5) & 63][idx & 31] = xr[i];
            }
        }
        __syncthreads();
    }
    // write partials: rowlocal = g*8 + p*2 + rr
    {
        const int rl0 = g * 8 + p * 2;
        float* z0 = &s.zsp[ks][rl0][bg * 4];
        float* z1 = &s.zsp[ks][rl0 + 1][bg * 4];
        *(float4*)z0 = make_float4(a0[0], a0[1], a0[2], a0[3]);
        *(float4*)z1 = make_float4(a1[0], a1[1], a1[2], a1[3]);
    }
    __syncthreads();
    // gate: 256 threads, thread = (hl, b)
    if (tid < 256) {
        const int hl = tid >> 5, b = tid & 31;
        const int h = h0 + hl;
        float z[4];
#pragma unroll
        for (int gg = 0; gg < 4; ++gg) {
            const int j = gg * 1024 + h;
            float sv = bih[j] + bhh[j];
#pragma unroll
            for (int q = 0; q < 4; ++q) sv += s.zsp[q][gg * 8 + hl][b];
            z[gg] = sv;
        }
        float c = cst[h * B + b];
        float cn = sigf(z[1]) * c + sigf(z[0]) * tanhf(z[2]);
        cst[h * B + b] = cn;
        float hv = sigf(z[3]) * tanhf(cn);
        hout[h * B + b] = hv;
        hbm[b * 1024 + h] = hv;
    }
}

// ---------------- energy phase: 128 blocks = (b, quarter), 128 t each ----------------
__device__ void energy_phase(const float* __restrict__ qw, const float* __restrict__ convw,
                             const float* __restrict__ loclin, const float* __restrict__ vw,
                             const int* __restrict__ lens, int cur, SAtt& s) {
    const int b = blockIdx.x >> 2;
    const int tbase = (blockIdx.x & 3) * 128;
    const int tid = threadIdx.x, warp = tid >> 5, lane = tid & 31;
    if (tid < 256) ((float4*)s.ahs)[tid] = ((const float4*)&g_ahbm[cur][b * ARNN])[tid];
    for (int i = tid; i < 158; i += NT) {
        int tp = tbase - 15 + i;
        bool ok = (tp >= 0 && tp < TIN);
        s.cat0[i] = ok ? g_aw[b * TIN + tp] : 0.f;
        s.cat1[i] = ok ? g_awc[b * TIN + tp] : 0.f;
    }
    for (int i = tid; i < 62 * LOCF; i += NT) s.cwsT[i >> 5][i & 31] = convw[(i & 31) * 62 + (i >> 5)];
    for (int i = tid; i < ATT * LOCF; i += NT) s.lls[i] = loclin[i];
    if (tid < ATT) s.vs[tid] = vw[tid];
    __syncthreads();
    // pq: 16 warps x 8 rows
#pragma unroll 1
    for (int r = 0; r < 8; ++r) {
        int a = warp * 8 + r;
        const float4* w = (const float4*)(qw + (size_t)a * ARNN);
        const float4* hv = (const float4*)s.ahs;
        float acc = 0.f;
#pragma unroll
        for (int i = 0; i < 8; ++i) {
            float4 wv = __ldg(&w[lane + i * 32]);
            float4 xv = hv[lane + i * 32];
            acc += wv.x * xv.x + wv.y * xv.y + wv.z * xv.z + wv.w * xv.w;
        }
        acc = wsum(acc);
        if (lane == 0) s.pqs[a] = acc;
    }
    // conv: thread (t = tid&127, fq = tid>>7) computes 8 filters
    {
        const int t = tid & 127, fq = tid >> 7;
        float lf[8];
#pragma unroll
        for (int i = 0; i < 8; ++i) lf[i] = 0.f;
#pragma unroll 2
        for (int kc = 0; kc < 62; ++kc) {
            float cv = (kc < 31) ? s.cat0[t + kc] : s.cat1[t + kc - 31];
            const float4* w = (const float4*)&s.cwsT[kc][fq * 8];
            float4 w0 = w[0], w1 = w[1];
            lf[0] += cv * w0.x; lf[1] += cv * w0.y; lf[2] += cv * w0.z; lf[3] += cv * w0.w;
            lf[4] += cv * w1.x; lf[5] += cv * w1.y; lf[6] += cv * w1.z; lf[7] += cv * w1.w;
        }
#pragma unroll
        for (int i = 0; i < 8; ++i) s.lfs[t][fq * 8 + i] = lf[i];
    }
    __syncthreads();
    // energies: thread (t, aq = tid>>7) handles 32 attention dims
    {
        const int t = tid & 127, aq = tid >> 7;
        float lfr[32];
#pragma unroll
        for (int i = 0; i < 32; ++i) lfr[i] = s.lfs[t][i];
        const float* pm = g_pmemT + (size_t)b * ATT * TIN + tbase + t;
        float e = 0.f;
#pragma unroll 2
        for (int a = aq * 32; a < aq * 32 + 32; ++a) {
            float s0 = s.pqs[a] + __ldg(&pm[(size_t)a * TIN]);
            const float4* ll = (const float4*)&s.lls[a * LOCF];
#pragma unroll
            for (int i = 0; i < 8; ++i) {
                float4 lv = ll[i];
                s0 += lv.x * lfr[i * 4] + lv.y * lfr[i * 4 + 1] + lv.z * lfr[i * 4 + 2] + lv.w * lfr[i * 4 + 3];
            }
            e += s.vs[a] * tanha(s0);
        }
        s.ep[tid] = e;
    }
    __syncthreads();
    if (tid < 128) {
        int tp = tbase + tid;
        float e = s.ep[tid] + s.ep[tid + 128] + s.ep[tid + 256] + s.ep[tid + 384];
        if (tp >= lens[b]) e = -1e9f;
        g_energy[b * TIN + tp] = e;
    }
}

// ---------------- softmax + partial context; q==3 blocks then do proj(t-1) ----------
__device__ void softctx_phase(const float* __restrict__ memory, int t, int cur,
                              float* __restrict__ out_align, SSoft& s) {
    const int b = blockIdx.x >> 2;
    const int q = blockIdx.x & 3;
    const int t0 = q * 128;
    const int tid = threadIdx.x, warp = tid >> 5, lane = tid & 31;
    float e = g_energy[b * TIN + tid];
    float m = wmax(e);
    if (lane == 0) s.red[warp] = m;
    __syncthreads();
    if (tid < 32) {
        float mm = (lane < 16) ? s.red[lane] : -3.4e38f;
        mm = wmax(mm);
        if (lane == 0) s.red[0] = mm;
    }
    __syncthreads();
    m = s.red[0];
    float p = __expf(e - m);
    float ps = wsum(p);
    __syncthreads();
    if (lane == 0) s.red[warp] = ps;
    __syncthreads();
    if (tid < 32) {
        float ss = (lane < 16) ? s.red[lane] : 0.f;
        ss = wsum(ss);
        if (lane == 0) s.red[0] = ss;
    }
    __syncthreads();
    float inv = __fdividef(1.f, s.red[0]);
    float aw = p * inv;
    s.sw[tid] = aw;
    if (tid >= t0 && tid < t0 + 128) {
        g_aw[b * TIN + tid] = aw;
        g_awc[b * TIN + tid] += aw;
        out_align[((size_t)b * TOUT + t) * TIN + tid] = aw;
    }
    __syncthreads();
    // partial context: this block covers t in [t0, t0+128), all 512 d (1 per thread)
    {
        const float* mb = memory + (size_t)b * TIN * ENC + (size_t)t0 * ENC + tid;
        float acc = 0.f;
#pragma unroll 4
        for (int tt = 0; tt < 128; ++tt)
            acc += s.sw[t0 + tt] * __ldg(&mb[(size_t)tt * ENC]);
        g_ctxpart[cur][q][tid * B + b] = acc;
    }
}

// ---------------- projection + gate for step tp (par = tp&1) ----------------
__device__ void proj_phase(const float* __restrict__ pw, const float* __restrict__ pb,
                           const float* __restrict__ gw, const float* __restrict__ gb,
                           int tp, int b, float* __restrict__ out_mel,
                           float* __restrict__ out_gate, SSoft& s) {
    const int par = tp & 1;
    const int tid = threadIdx.x, warp = tid >> 5, lane = tid & 31;
    __syncthreads();
    for (int i = tid; i < DRNN; i += NT) s.sd[i] = g_dhbm[par][b * DRNN + i];
    for (int i = tid; i < ENC; i += NT) {
        const float* pp = &g_ctxpart[par][0][i * B + b];
        s.sd[DRNN + i] = pp[0] + pp[ENC * B] + pp[2 * ENC * B] + pp[3 * ENC * B];
    }
    __syncthreads();
    for (int r = warp; r < NMEL + 1; r += 16) {
        const float4* w = (const float4*)((r < NMEL) ? (pw + (size_t)r * (DRNN + ENC)) : gw);
        const float4* x = (const float4*)s.sd;
        float acc = 0.f;
#pragma unroll
        for (int i = 0; i < 12; ++i) {
            float4 wv = __ldg(&w[lane + i * 32]);
            float4 xv = x[lane + i * 32];
            acc += wv.x * xv.x + wv.y * xv.y + wv.z * xv.z + wv.w * xv.w;
        }
        acc = wsum(acc);
        if (lane == 0) {
            if (r < NMEL) out_mel[(size_t)b * NMEL * TOUT + (size_t)r * TOUT + tp] = acc + pb[r];
            else out_gate[(size_t)b * TOUT + tp] = acc + gb[0];
        }
    }
}

// ---------------- persistent decoder ----------------
__global__ __launch_bounds__(NT, 1)
void persist_kernel(const float* __restrict__ memory,
                    const float* __restrict__ awih, const float* __restrict__ awhh,
                    const float* __restrict__ abih, const float* __restrict__ abhh,
                    const float* __restrict__ qw, const float* __restrict__ vw,
                    const float* __restrict__ convw, const float* __restrict__ loclin,
                    const float* __restrict__ dwih, const float* __restrict__ dwhh,
                    const float* __restrict__ dbih, const float* __restrict__ dbhh,
                    const float* __restrict__ pw, const float* __restrict__ pb,
                    const float* __restrict__ gw, const float* __restrict__ gb,
                    const int* __restrict__ lens,
                    float* __restrict__ out_mel, float* __restrict__ out_gate,
                    float* __restrict__ out_align) {
    extern __shared__ __align__(16) char smraw[];
    Smem& sm = *reinterpret_cast<Smem*>(smraw);
    for (int t = 0; t < TOUT; ++t) {
        const int cur = t & 1, prev = cur ^ 1;
        // phase 1: attention LSTM (srcB = actx(t-1) = ctxpart[prev])
        lstm_fused<PRE, ENC>(g_pren + (size_t)t * PRE * B, g_ctxpart[prev][0], &g_ah[prev][0],
                             awih, awhh, abih, abhh, g_ac, &g_ah[cur][0], &g_ahbm[cur][0], sm.l);
        gbar();
        // phase 2: attention energies
        energy_phase(qw, convw, loclin, vw, lens, cur, sm.a);
        gbar();
        // phase 3: softmax + partial context; q==3 blocks also run proj(t-1)
        softctx_phase(memory, t, cur, out_align, sm.s);
        if ((blockIdx.x & 3) == 3 && t > 0)
            proj_phase(pw, pb, gw, gb, t - 1, blockIdx.x >> 2, out_mel, out_gate, sm.s);
        gbar();
        // phase 4: decoder LSTM (srcA = ah(t), srcB = actx(t) = ctxpart[cur])
        lstm_fused<ARNN, ENC>(&g_ah[cur][0], g_ctxpart[cur][0], &g_dh[prev][0],
                              dwih, dwhh, dbih, dbhh, g_dc, &g_dh[cur][0], &g_dhbm[cur][0], sm.l);
        gbar();
    }
    // final projection for t = TOUT-1
    if (blockIdx.x < 32)
        proj_phase(pw, pb, gw, gb, TOUT - 1, blockIdx.x, out_mel, out_gate, sm.s);
}

// ---------------- launch ----------------
extern "C" void kernel_launch(void* const* d_in, const int* in_sizes, int n_in,
                              void* d_out, int out_size) {
    const float* memory = (const float*)d_in[0];
    const float* dec    = (const float*)d_in[1];
    const float* w1     = (const float*)d_in[2];
    const float* w2     = (const float*)d_in[3];
    const float* awih   = (const float*)d_in[4];
    const float* awhh   = (const float*)d_in[5];
    const float* abih   = (const float*)d_in[6];
    const float* abhh   = (const float*)d_in[7];
    const float* qw     = (const float*)d_in[8];
    const float* memw   = (const float*)d_in[9];
    const float* vw     = (const float*)d_in[10];
    const float* convw  = (const float*)d_in[11];
    const float* loclin = (const float*)d_in[12];
    const float* dwih   = (const float*)d_in[13];
    const float* dwhh   = (const float*)d_in[14];
    const float* dbih   = (const float*)d_in[15];
    const float* dbhh   = (const float*)d_in[16];
    const float* pw     = (const float*)d_in[17];
    const float* pb     = (const float*)d_in[18];
    const float* gw     = (const float*)d_in[19];
    const float* gb     = (const float*)d_in[20];
    const int*   lens   = (const int*)d_in[21];

    float* out_mel = (float*)d_out;
    float* out_gate = out_mel + (size_t)B * NMEL * TOUT;
    float* out_align = out_gate + (size_t)B * TOUT;

    cudaFuncSetAttribute(persist_kernel, cudaFuncAttributeMaxDynamicSharedMemorySize,
                         (int)sizeof(Smem));

    zero_kernel<<<(4 * ENC * B + 255) / 256, 256>>>();
    prenet_kernel<<<TOUT * B, 256>>>(dec, w1, w2);
    pmem_kernel<<<dim3(B, TIN / 16), 128>>>(memory, memw);
    persist_kernel<<<NB, NT, sizeof(Smem)>>>(memory, awih, awhh, abih, abhh, qw, vw,
                                             convw, loclin, dwih, dwhh, dbih, dbhh,
                                             pw, pb, gw, gb, lens,
                                             out_mel, out_gate, out_align);
}